// round 1
// baseline (speedup 1.0000x reference)
#include <cuda_runtime.h>
#include <math.h>

#define BB 2
#define SS 2048
#define DD 1024
#define HH 16
#define HDD 64

// Scratch (device globals: no runtime allocation allowed)
__device__ float g_qkv[(size_t)BB * SS * 3 * DD];   // [B*S, 3D]
__device__ float g_att[(size_t)BB * SS * DD];       // [B*S, D]

// ---------------------------------------------------------------------------
// SGEMM: C[M,N] = A[M,K] @ B[K,N] + bias[N]
// 128x128 block tile, BK=16, 256 threads, 8x8 per-thread microtile.
// All problem dims here are multiples of the tile sizes (no guards needed).
// ---------------------------------------------------------------------------
__global__ void __launch_bounds__(256) sgemm_bias(
    const float* __restrict__ A, const float* __restrict__ Bw,
    const float* __restrict__ bias, float* __restrict__ C,
    int M, int N, int K)
{
    __shared__ float As[16][129];   // transposed A tile, +1 pad for store conflicts
    __shared__ float Bs[16][128];

    const int tid = threadIdx.x;
    const int tx = tid & 15, ty = tid >> 4;
    const int m0 = blockIdx.y << 7;
    const int n0 = blockIdx.x << 7;

    float acc[8][8];
#pragma unroll
    for (int i = 0; i < 8; i++)
#pragma unroll
        for (int j = 0; j < 8; j++) acc[i][j] = 0.f;

    for (int kt = 0; kt < K; kt += 16) {
        // Load A tile (128 rows x 16 cols), store transposed As[k][m]
#pragma unroll
        for (int t = 0; t < 2; t++) {
            int idx = tid + (t << 8);
            int row = idx >> 2;            // 0..127
            int c4  = (idx & 3) << 2;      // 0,4,8,12
            float4 a = *(const float4*)(A + (size_t)(m0 + row) * K + kt + c4);
            As[c4 + 0][row] = a.x;
            As[c4 + 1][row] = a.y;
            As[c4 + 2][row] = a.z;
            As[c4 + 3][row] = a.w;
        }
        // Load B tile (16 rows x 128 cols)
#pragma unroll
        for (int t = 0; t < 2; t++) {
            int idx = tid + (t << 8);
            int row = idx >> 5;            // 0..15
            int c4  = (idx & 31) << 2;     // 0..124
            *(float4*)&Bs[row][c4] =
                *(const float4*)(Bw + (size_t)(kt + row) * N + n0 + c4);
        }
        __syncthreads();

#pragma unroll
        for (int k = 0; k < 16; k++) {
            float ra[8], rb[8];
#pragma unroll
            for (int i = 0; i < 8; i++) ra[i] = As[k][(ty << 3) + i];
            *(float4*)&rb[0] = *(const float4*)&Bs[k][(tx << 3)];
            *(float4*)&rb[4] = *(const float4*)&Bs[k][(tx << 3) + 4];
#pragma unroll
            for (int i = 0; i < 8; i++)
#pragma unroll
                for (int j = 0; j < 8; j++)
                    acc[i][j] = fmaf(ra[i], rb[j], acc[i][j]);
        }
        __syncthreads();
    }

    float bj[8];
#pragma unroll
    for (int j = 0; j < 8; j++) bj[j] = bias[n0 + (tx << 3) + j];

#pragma unroll
    for (int i = 0; i < 8; i++) {
        float* cp = C + (size_t)(m0 + (ty << 3) + i) * N + n0 + (tx << 3);
        float4 o0 = make_float4(acc[i][0] + bj[0], acc[i][1] + bj[1],
                                acc[i][2] + bj[2], acc[i][3] + bj[3]);
        float4 o1 = make_float4(acc[i][4] + bj[4], acc[i][5] + bj[5],
                                acc[i][6] + bj[6], acc[i][7] + bj[7]);
        *(float4*)cp       = o0;
        *(float4*)(cp + 4) = o1;
    }
}

// ---------------------------------------------------------------------------
// Flash attention (fp32, causal).
// Block = (q-tile of 64 rows, head, batch). 256 threads, each owns a 4x4
// microtile of the 64x64 score tile and of the 64x64 output tile.
// Smem: Qs[64][64] + KP[64*64] (K tile, reused for P) + Vs[64][64] = 48 KB.
// KP uses col XOR (row&31) swizzle -> ~2-way max conflicts without padding.
// ---------------------------------------------------------------------------
__global__ void __launch_bounds__(256) flash_attn(
    const float* __restrict__ qkv, float* __restrict__ out)
{
    __shared__ float Qs[64][64];
    __shared__ float KP[64 * 64];
    __shared__ float Vs[64][64];

    const int tid = threadIdx.x;
    const int tx = tid & 15, ty = tid >> 4;
    const int qt = blockIdx.x;     // q tile 0..31
    const int h  = blockIdx.y;
    const int b  = blockIdx.z;
    const int q0 = qt << 6;
    const size_t rstride = 3 * DD;

    const float* qp = qkv + (size_t)(b * SS + q0) * rstride + h * HDD;

    // Load Q tile (coalesced, float4)
#pragma unroll
    for (int t = 0; t < 4; t++) {
        int row = (tid >> 4) + (t << 4);
        int c4  = (tid & 15) << 2;
        *(float4*)&Qs[row][c4] = *(const float4*)(qp + (size_t)row * rstride + c4);
    }

    float acc[4][4];
    float m_i[4], l_i[4];
#pragma unroll
    for (int i = 0; i < 4; i++) {
        m_i[i] = -INFINITY; l_i[i] = 0.f;
#pragma unroll
        for (int j = 0; j < 4; j++) acc[i][j] = 0.f;
    }

    for (int kt = 0; kt <= qt; kt++) {
        const int k0 = kt << 6;
        const float* kp = qkv + (size_t)(b * SS + k0) * rstride + DD + h * HDD;

        __syncthreads();   // protect KP/Vs from prior-tile readers (also covers Q on iter 0)

        // Load K (swizzled into KP) and V tiles
#pragma unroll
        for (int t = 0; t < 4; t++) {
            int row = (tid >> 4) + (t << 4);
            int c4  = (tid & 15) << 2;
            const float* src = kp + (size_t)row * rstride + c4;
            float4 kv = *(const float4*)src;
            int sw = row & 31;
            KP[(row << 6) + ((c4 + 0) ^ sw)] = kv.x;
            KP[(row << 6) + ((c4 + 1) ^ sw)] = kv.y;
            KP[(row << 6) + ((c4 + 2) ^ sw)] = kv.z;
            KP[(row << 6) + ((c4 + 3) ^ sw)] = kv.w;
            *(float4*)&Vs[row][c4] = *(const float4*)(src + DD);  // V = K ptr + D
        }
        __syncthreads();

        // S = Q K^T
        float s[4][4];
#pragma unroll
        for (int i = 0; i < 4; i++)
#pragma unroll
            for (int j = 0; j < 4; j++) s[i][j] = 0.f;

#pragma unroll 8
        for (int d = 0; d < 64; d++) {
            float qr[4], kr[4];
#pragma unroll
            for (int i = 0; i < 4; i++) qr[i] = Qs[(ty << 2) + i][d];
#pragma unroll
            for (int j = 0; j < 4; j++) {
                int n = (tx << 2) + j;
                kr[j] = KP[(n << 6) + (d ^ (n & 31))];
            }
#pragma unroll
            for (int i = 0; i < 4; i++)
#pragma unroll
                for (int j = 0; j < 4; j++)
                    s[i][j] = fmaf(qr[i], kr[j], s[i][j]);
        }

        // Scale + causal mask (only the diagonal tile needs masking)
        const bool diag = (kt == qt);
#pragma unroll
        for (int i = 0; i < 4; i++) {
            int r = q0 + (ty << 2) + i;
#pragma unroll
            for (int j = 0; j < 4; j++) {
                float v = s[i][j] * 0.125f;   // 1/sqrt(64)
                if (diag && (k0 + (tx << 2) + j) > r) v = -1e30f;
                s[i][j] = v;
            }
        }

        // Online softmax (row stats reduced across the 16 tx lanes)
#pragma unroll
        for (int i = 0; i < 4; i++) {
            float mloc = fmaxf(fmaxf(s[i][0], s[i][1]), fmaxf(s[i][2], s[i][3]));
#pragma unroll
            for (int off = 8; off; off >>= 1)
                mloc = fmaxf(mloc, __shfl_xor_sync(0xffffffffu, mloc, off, 16));
            float mnew = fmaxf(m_i[i], mloc);
            float corr = __expf(m_i[i] - mnew);
            m_i[i] = mnew;
            float rs = 0.f;
#pragma unroll
            for (int j = 0; j < 4; j++) {
                float p = __expf(s[i][j] - mnew);
                s[i][j] = p;
                rs += p;
            }
#pragma unroll
            for (int off = 8; off; off >>= 1)
                rs += __shfl_xor_sync(0xffffffffu, rs, off, 16);
            l_i[i] = l_i[i] * corr + rs;
#pragma unroll
            for (int j = 0; j < 4; j++) acc[i][j] *= corr;
        }

        __syncthreads();   // all threads done reading K from KP

        // Write P into KP (same swizzle)
#pragma unroll
        for (int i = 0; i < 4; i++) {
            int r = (ty << 2) + i;
            int sw = r & 31;
#pragma unroll
            for (int j = 0; j < 4; j++)
                KP[(r << 6) + (((tx << 2) + j) ^ sw)] = s[i][j];
        }
        __syncthreads();

        // O += P @ V
#pragma unroll 8
        for (int k = 0; k < 64; k++) {
            float pr[4];
#pragma unroll
            for (int i = 0; i < 4; i++) {
                int r = (ty << 2) + i;
                pr[i] = KP[(r << 6) + (k ^ (r & 31))];
            }
            float4 vv = *(const float4*)&Vs[k][tx << 2];
#pragma unroll
            for (int i = 0; i < 4; i++) {
                acc[i][0] = fmaf(pr[i], vv.x, acc[i][0]);
                acc[i][1] = fmaf(pr[i], vv.y, acc[i][1]);
                acc[i][2] = fmaf(pr[i], vv.z, acc[i][2]);
                acc[i][3] = fmaf(pr[i], vv.w, acc[i][3]);
            }
        }
    }

    // Normalize and write merged-head output [B*S, D]
    float* op = out + (size_t)(b * SS + q0) * DD + h * HDD;
#pragma unroll
    for (int i = 0; i < 4; i++) {
        float inv = 1.f / l_i[i];
        float4 o = make_float4(acc[i][0] * inv, acc[i][1] * inv,
                               acc[i][2] * inv, acc[i][3] * inv);
        *(float4*)(op + (size_t)((ty << 2) + i) * DD + (tx << 2)) = o;
    }
}

// ---------------------------------------------------------------------------
extern "C" void kernel_launch(void* const* d_in, const int* in_sizes, int n_in,
                              void* d_out, int out_size)
{
    const float* x  = (const float*)d_in[0];   // hidden_states [B,S,D]
    const float* w1 = (const float*)d_in[1];   // c_attn_w [D, 3D]
    const float* b1 = (const float*)d_in[2];   // c_attn_b [3D]
    const float* w2 = (const float*)d_in[3];   // c_proj_w [D, D]
    const float* b2 = (const float*)d_in[4];   // c_proj_b [D]
    float* out = (float*)d_out;

    float *qkv = nullptr, *att = nullptr;
    cudaGetSymbolAddress((void**)&qkv, g_qkv);
    cudaGetSymbolAddress((void**)&att, g_att);

    const int M = BB * SS;   // 4096

    // 1) QKV projection: [4096,1024] @ [1024,3072] + b1
    sgemm_bias<<<dim3(3 * DD / 128, M / 128), 256>>>(x, w1, b1, qkv, M, 3 * DD, DD);

    // 2) Causal flash attention per (q-tile, head, batch)
    flash_attn<<<dim3(SS / 64, HH, BB), 256>>>(qkv, att);

    // 3) Output projection: [4096,1024] @ [1024,1024] + b2
    sgemm_bias<<<dim3(DD / 128, M / 128), 256>>>(att, w2, b2, out, M, DD, DD);
}

// round 3
// speedup vs baseline: 1.4284x; 1.4284x over previous
#include <cuda_runtime.h>
#include <cuda_bf16.h>
#include <math.h>
#include <stdint.h>

#define BB 2
#define SS 2048
#define DD 1024
#define HH 16
#define HDD 64
#define MM (BB*SS)          // 4096
#define KK DD               // 1024

// ---------------- device scratch (no runtime allocation allowed) ----------------
__device__ float g_qkv[(size_t)MM * 3 * DD];          // fp32 qkv for flash attn
__device__ __nv_bfloat16 g_xhi[(size_t)MM * KK];
__device__ __nv_bfloat16 g_xlo[(size_t)MM * KK];
__device__ __nv_bfloat16 g_w1hi[(size_t)3 * DD * KK]; // transposed [3D, K]
__device__ __nv_bfloat16 g_w1lo[(size_t)3 * DD * KK];
__device__ __nv_bfloat16 g_w2hi[(size_t)DD * KK];     // transposed [D, K]
__device__ __nv_bfloat16 g_w2lo[(size_t)DD * KK];
__device__ __nv_bfloat16 g_ahi[(size_t)MM * DD];      // attention out hi
__device__ __nv_bfloat16 g_alo[(size_t)MM * DD];      // attention out lo

// ---------------- PTX helpers (base sm_80+ ISA only — no 'a' features) ----------
__device__ __forceinline__ uint32_t smem_u32(const void* p) {
    uint32_t a;
    asm("{ .reg .u64 t; cvta.to.shared.u64 t, %1; cvt.u32.u64 %0, t; }" : "=r"(a) : "l"(p));
    return a;
}
__device__ __forceinline__ void cp16(uint32_t dst, const void* src) {
    asm volatile("cp.async.cg.shared.global [%0], [%1], 16;" :: "r"(dst), "l"(src));
}
__device__ __forceinline__ void cp_commit() {
    asm volatile("cp.async.commit_group;" ::: "memory");
}
template <int N>
__device__ __forceinline__ void cp_wait() {
    asm volatile("cp.async.wait_group %0;" :: "n"(N) : "memory");
}
__device__ __forceinline__ void ldsm4(uint32_t* r, uint32_t addr) {
    asm volatile("ldmatrix.sync.aligned.m8n8.x4.shared.b16 {%0,%1,%2,%3}, [%4];"
                 : "=r"(r[0]), "=r"(r[1]), "=r"(r[2]), "=r"(r[3]) : "r"(addr));
}
__device__ __forceinline__ void mma16816(float* d, const uint32_t* a, const uint32_t* b) {
    asm volatile(
        "mma.sync.aligned.m16n8k16.row.col.f32.bf16.bf16.f32 "
        "{%0,%1,%2,%3}, {%4,%5,%6,%7}, {%8,%9}, {%0,%1,%2,%3};"
        : "+f"(d[0]), "+f"(d[1]), "+f"(d[2]), "+f"(d[3])
        : "r"(a[0]), "r"(a[1]), "r"(a[2]), "r"(a[3]), "r"(b[0]), "r"(b[1]));
}

// smem tile: [row][32 bf16] = 64B/row; 16B chunk index swizzled by ((row>>1)&3)
__device__ __forceinline__ uint32_t swz(int row, int c) {
    return (uint32_t)(row * 64 + ((c ^ ((row >> 1) & 3)) << 4));
}

#define TILE_BYTES 8192          // 128 rows x 32 bf16 x 2B
#define STAGE_BYTES (4 * TILE_BYTES)
#define GEMM_SMEM  (2 * STAGE_BYTES)   // 64 KB

// ---------------------------------------------------------------------------
// bf16x3 tensor-core GEMM via mma.sync:
//   C[M,N] = (Ahi+Alo)[M,K] @ (Bhi+Blo)[N,K]^T + bias,   K = 1024
// CTA 128x128, BK=32, 256 threads (8 warps, 2x4 -> 64x32 each), cp.async x2.
// ---------------------------------------------------------------------------
__global__ void __launch_bounds__(256, 1) gemm_mma(
    const __nv_bfloat16* __restrict__ Ahi, const __nv_bfloat16* __restrict__ Alo,
    const __nv_bfloat16* __restrict__ Bhi, const __nv_bfloat16* __restrict__ Blo,
    const float* __restrict__ bias, float* __restrict__ C, int N)
{
    extern __shared__ char smem[];
    const uint32_t sbase = smem_u32(smem);
    const int tid  = threadIdx.x;
    const int wid  = tid >> 5;
    const int lane = tid & 31;
    const int wm = (wid >> 2) * 64;   // warp m offset in tile
    const int wn = (wid & 3) * 32;    // warp n offset in tile
    const int m0 = blockIdx.y << 7;
    const int n0 = blockIdx.x << 7;

    const __nv_bfloat16* srcs[4] = {
        Ahi + (size_t)m0 * KK, Alo + (size_t)m0 * KK,
        Bhi + (size_t)n0 * KK, Blo + (size_t)n0 * KK };

    // prefetch lambda-ish macro: stage s <- k-tile kt
    auto prefetch = [&](int kt, int s) {
        uint32_t stb = sbase + s * STAGE_BYTES;
#pragma unroll
        for (int t = 0; t < 4; t++) {
            const __nv_bfloat16* g = srcs[t] + kt * 32;
#pragma unroll
            for (int i = 0; i < 2; i++) {
                int cid = i * 256 + tid;
                int row = cid >> 2, c = cid & 3;
                cp16(stb + t * TILE_BYTES + swz(row, c),
                     g + (size_t)row * KK + c * 8);
            }
        }
    };

    float acc[4][4][4];
#pragma unroll
    for (int i = 0; i < 4; i++)
#pragma unroll
        for (int j = 0; j < 4; j++)
#pragma unroll
            for (int k = 0; k < 4; k++) acc[i][j][k] = 0.f;

    prefetch(0, 0);
    cp_commit();

    const int KCH = KK / 32;   // 32
    for (int kt = 0; kt < KCH; kt++) {
        const int s = kt & 1;
        if (kt + 1 < KCH) {
            prefetch(kt + 1, s ^ 1);
            cp_commit();
            cp_wait<1>();
        } else {
            cp_wait<0>();
        }
        __syncthreads();

        const uint32_t ahb = sbase + s * STAGE_BYTES;
        const uint32_t alb = ahb + TILE_BYTES;
        const uint32_t bhb = ahb + 2 * TILE_BYTES;
        const uint32_t blb = ahb + 3 * TILE_BYTES;

#pragma unroll
        for (int kh = 0; kh < 2; kh++) {
            const int lrow = lane & 15;
            const int lkc  = kh * 2 + (lane >> 4);

            uint32_t ah[4][4], al[4][4];
#pragma unroll
            for (int mt = 0; mt < 4; mt++) {
                uint32_t off = swz(wm + mt * 16 + lrow, lkc);
                ldsm4(ah[mt], ahb + off);
                ldsm4(al[mt], alb + off);
            }
            uint32_t bh[4][2], bl[4][2];
#pragma unroll
            for (int np = 0; np < 2; np++) {
                uint32_t off = swz(wn + np * 16 + lrow, lkc);
                uint32_t r[4];
                ldsm4(r, bhb + off);
                bh[np * 2][0] = r[0]; bh[np * 2][1] = r[2];
                bh[np * 2 + 1][0] = r[1]; bh[np * 2 + 1][1] = r[3];
                ldsm4(r, blb + off);
                bl[np * 2][0] = r[0]; bl[np * 2][1] = r[2];
                bl[np * 2 + 1][0] = r[1]; bl[np * 2 + 1][1] = r[3];
            }
#pragma unroll
            for (int mt = 0; mt < 4; mt++)
#pragma unroll
                for (int nt = 0; nt < 4; nt++) {
                    mma16816(acc[mt][nt], ah[mt], bh[nt]);
                    mma16816(acc[mt][nt], ah[mt], bl[nt]);
                    mma16816(acc[mt][nt], al[mt], bh[nt]);
                }
        }
        __syncthreads();
    }

    // epilogue: acc frag (m16n8): d0,d1 -> row lane>>2, cols (lane&3)*2,+1; d2,d3 -> row+8
#pragma unroll
    for (int mt = 0; mt < 4; mt++) {
#pragma unroll
        for (int nt = 0; nt < 4; nt++) {
            int row = m0 + wm + mt * 16 + (lane >> 2);
            int col = n0 + wn + nt * 8 + ((lane & 3) << 1);
            float b0 = __ldg(bias + col), b1 = __ldg(bias + col + 1);
            float* d = acc[mt][nt];
            *(float2*)(C + (size_t)row * N + col) =
                make_float2(d[0] + b0, d[1] + b1);
            *(float2*)(C + (size_t)(row + 8) * N + col) =
                make_float2(d[2] + b0, d[3] + b1);
        }
    }
}

// ---------------------------------------------------------------------------
// fp32 -> bf16 hi/lo split (elementwise, float4-vectorized)
// ---------------------------------------------------------------------------
__global__ void split_f32(const float* __restrict__ in,
                          __nv_bfloat16* __restrict__ hi,
                          __nv_bfloat16* __restrict__ lo, int n4)
{
    int i = blockIdx.x * blockDim.x + threadIdx.x;
    if (i >= n4) return;
    float4 v = ((const float4*)in)[i];
    __nv_bfloat16 h[4], l[4];
    float f[4] = { v.x, v.y, v.z, v.w };
#pragma unroll
    for (int j = 0; j < 4; j++) {
        h[j] = __float2bfloat16(f[j]);
        l[j] = __float2bfloat16(f[j] - __bfloat162float(h[j]));
    }
    ((uint2*)hi)[i] = *(uint2*)h;
    ((uint2*)lo)[i] = *(uint2*)l;
}

// ---------------------------------------------------------------------------
// W[K,N] fp32 -> transposed bf16 hi/lo [N,K]
// ---------------------------------------------------------------------------
__global__ void transpose_split(const float* __restrict__ in,
                                __nv_bfloat16* __restrict__ hi,
                                __nv_bfloat16* __restrict__ lo, int K, int N)
{
    __shared__ float t[32][33];
    int bx = blockIdx.x << 5;   // N offset
    int by = blockIdx.y << 5;   // K offset
    int tx = threadIdx.x, ty = threadIdx.y;
#pragma unroll
    for (int i = 0; i < 32; i += 8)
        t[ty + i][tx] = in[(size_t)(by + ty + i) * N + bx + tx];
    __syncthreads();
#pragma unroll
    for (int i = 0; i < 32; i += 8) {
        float v = t[tx][ty + i];
        int n = bx + ty + i, k = by + tx;
        __nv_bfloat16 h = __float2bfloat16(v);
        hi[(size_t)n * K + k] = h;
        lo[(size_t)n * K + k] = __float2bfloat16(v - __bfloat162float(h));
    }
}

// ---------------------------------------------------------------------------
// Flash attention (fp32, causal) — same math as the passing R1 kernel,
// output emitted as bf16 hi/lo for the tensor-core projection GEMM.
// ---------------------------------------------------------------------------
__global__ void __launch_bounds__(256) flash_attn(
    const float* __restrict__ qkv,
    __nv_bfloat16* __restrict__ out_hi, __nv_bfloat16* __restrict__ out_lo)
{
    __shared__ float Qs[64][64];
    __shared__ float KP[64 * 64];
    __shared__ float Vs[64][64];

    const int tid = threadIdx.x;
    const int tx = tid & 15, ty = tid >> 4;
    const int qt = blockIdx.x;
    const int h  = blockIdx.y;
    const int b  = blockIdx.z;
    const int q0 = qt << 6;
    const size_t rstride = 3 * DD;

    const float* qp = qkv + (size_t)(b * SS + q0) * rstride + h * HDD;

#pragma unroll
    for (int t = 0; t < 4; t++) {
        int row = (tid >> 4) + (t << 4);
        int c4  = (tid & 15) << 2;
        *(float4*)&Qs[row][c4] = *(const float4*)(qp + (size_t)row * rstride + c4);
    }

    float acc[4][4];
    float m_i[4], l_i[4];
#pragma unroll
    for (int i = 0; i < 4; i++) {
        m_i[i] = -INFINITY; l_i[i] = 0.f;
#pragma unroll
        for (int j = 0; j < 4; j++) acc[i][j] = 0.f;
    }

    for (int kt = 0; kt <= qt; kt++) {
        const int k0 = kt << 6;
        const float* kp = qkv + (size_t)(b * SS + k0) * rstride + DD + h * HDD;

        __syncthreads();

#pragma unroll
        for (int t = 0; t < 4; t++) {
            int row = (tid >> 4) + (t << 4);
            int c4  = (tid & 15) << 2;
            const float* src = kp + (size_t)row * rstride + c4;
            float4 kv = *(const float4*)src;
            int sw = row & 31;
            KP[(row << 6) + ((c4 + 0) ^ sw)] = kv.x;
            KP[(row << 6) + ((c4 + 1) ^ sw)] = kv.y;
            KP[(row << 6) + ((c4 + 2) ^ sw)] = kv.z;
            KP[(row << 6) + ((c4 + 3) ^ sw)] = kv.w;
            *(float4*)&Vs[row][c4] = *(const float4*)(src + DD);
        }
        __syncthreads();

        float s[4][4];
#pragma unroll
        for (int i = 0; i < 4; i++)
#pragma unroll
            for (int j = 0; j < 4; j++) s[i][j] = 0.f;

#pragma unroll 8
        for (int d = 0; d < 64; d++) {
            float qr[4], kr[4];
#pragma unroll
            for (int i = 0; i < 4; i++) qr[i] = Qs[(ty << 2) + i][d];
#pragma unroll
            for (int j = 0; j < 4; j++) {
                int n = (tx << 2) + j;
                kr[j] = KP[(n << 6) + (d ^ (n & 31))];
            }
#pragma unroll
            for (int i = 0; i < 4; i++)
#pragma unroll
                for (int j = 0; j < 4; j++)
                    s[i][j] = fmaf(qr[i], kr[j], s[i][j]);
        }

        const bool diag = (kt == qt);
#pragma unroll
        for (int i = 0; i < 4; i++) {
            int r = q0 + (ty << 2) + i;
#pragma unroll
            for (int j = 0; j < 4; j++) {
                float v = s[i][j] * 0.125f;
                if (diag && (k0 + (tx << 2) + j) > r) v = -1e30f;
                s[i][j] = v;
            }
        }

#pragma unroll
        for (int i = 0; i < 4; i++) {
            float mloc = fmaxf(fmaxf(s[i][0], s[i][1]), fmaxf(s[i][2], s[i][3]));
#pragma unroll
            for (int off = 8; off; off >>= 1)
                mloc = fmaxf(mloc, __shfl_xor_sync(0xffffffffu, mloc, off, 16));
            float mnew = fmaxf(m_i[i], mloc);
            float corr = __expf(m_i[i] - mnew);
            m_i[i] = mnew;
            float rs = 0.f;
#pragma unroll
            for (int j = 0; j < 4; j++) {
                float p = __expf(s[i][j] - mnew);
                s[i][j] = p;
                rs += p;
            }
#pragma unroll
            for (int off = 8; off; off >>= 1)
                rs += __shfl_xor_sync(0xffffffffu, rs, off, 16);
            l_i[i] = l_i[i] * corr + rs;
#pragma unroll
            for (int j = 0; j < 4; j++) acc[i][j] *= corr;
        }

        __syncthreads();

#pragma unroll
        for (int i = 0; i < 4; i++) {
            int r = (ty << 2) + i;
            int sw = r & 31;
#pragma unroll
            for (int j = 0; j < 4; j++)
                KP[(r << 6) + (((tx << 2) + j) ^ sw)] = s[i][j];
        }
        __syncthreads();

#pragma unroll 8
        for (int k = 0; k < 64; k++) {
            float pr[4];
#pragma unroll
            for (int i = 0; i < 4; i++) {
                int r = (ty << 2) + i;
                pr[i] = KP[(r << 6) + (k ^ (r & 31))];
            }
            float4 vv = *(const float4*)&Vs[k][tx << 2];
#pragma unroll
            for (int i = 0; i < 4; i++) {
                acc[i][0] = fmaf(pr[i], vv.x, acc[i][0]);
                acc[i][1] = fmaf(pr[i], vv.y, acc[i][1]);
                acc[i][2] = fmaf(pr[i], vv.z, acc[i][2]);
                acc[i][3] = fmaf(pr[i], vv.w, acc[i][3]);
            }
        }
    }

    // normalize + split to bf16 hi/lo, merged-head layout [B*S, D]
    size_t obase = (size_t)(b * SS + q0) * DD + h * HDD + (tx << 2);
#pragma unroll
    for (int i = 0; i < 4; i++) {
        float inv = 1.f / l_i[i];
        float f[4] = { acc[i][0] * inv, acc[i][1] * inv,
                       acc[i][2] * inv, acc[i][3] * inv };
        __nv_bfloat16 hh[4], ll[4];
#pragma unroll
        for (int j = 0; j < 4; j++) {
            hh[j] = __float2bfloat16(f[j]);
            ll[j] = __float2bfloat16(f[j] - __bfloat162float(hh[j]));
        }
        size_t o = obase + (size_t)((ty << 2) + i) * DD;
        *(uint2*)(out_hi + o) = *(uint2*)hh;
        *(uint2*)(out_lo + o) = *(uint2*)ll;
    }
}

// ---------------------------------------------------------------------------
extern "C" void kernel_launch(void* const* d_in, const int* in_sizes, int n_in,
                              void* d_out, int out_size)
{
    const float* x  = (const float*)d_in[0];
    const float* w1 = (const float*)d_in[1];
    const float* b1 = (const float*)d_in[2];
    const float* w2 = (const float*)d_in[3];
    const float* b2 = (const float*)d_in[4];
    float* out = (float*)d_out;

    float* qkv; __nv_bfloat16 *xhi, *xlo, *w1hi, *w1lo, *w2hi, *w2lo, *ahi, *alo;
    cudaGetSymbolAddress((void**)&qkv,  g_qkv);
    cudaGetSymbolAddress((void**)&xhi,  g_xhi);
    cudaGetSymbolAddress((void**)&xlo,  g_xlo);
    cudaGetSymbolAddress((void**)&w1hi, g_w1hi);
    cudaGetSymbolAddress((void**)&w1lo, g_w1lo);
    cudaGetSymbolAddress((void**)&w2hi, g_w2hi);
    cudaGetSymbolAddress((void**)&w2lo, g_w2lo);
    cudaGetSymbolAddress((void**)&ahi,  g_ahi);
    cudaGetSymbolAddress((void**)&alo,  g_alo);

    static int smem_set = 0;
    if (!smem_set) {
        cudaFuncSetAttribute(gemm_mma,
            cudaFuncAttributeMaxDynamicSharedMemorySize, GEMM_SMEM);
        smem_set = 1;
    }

    // 0) operand preparation
    split_f32<<<(MM * KK / 4 + 255) / 256, 256>>>(x, xhi, xlo, MM * KK / 4);
    transpose_split<<<dim3(3 * DD / 32, KK / 32), dim3(32, 8)>>>(w1, w1hi, w1lo, KK, 3 * DD);
    transpose_split<<<dim3(DD / 32, KK / 32), dim3(32, 8)>>>(w2, w2hi, w2lo, KK, DD);

    // 1) QKV projection (tensor cores): [4096,1024] @ [1024,3072] + b1 -> fp32 qkv
    gemm_mma<<<dim3(3 * DD / 128, MM / 128), 256, GEMM_SMEM>>>(
        xhi, xlo, w1hi, w1lo, b1, qkv, 3 * DD);

    // 2) causal flash attention (fp32), writes bf16 hi/lo attention output
    flash_attn<<<dim3(SS / 64, HH, BB), 256>>>(qkv, ahi, alo);

    // 3) output projection (tensor cores): [4096,1024] @ [1024,1024] + b2 -> out
    gemm_mma<<<dim3(DD / 128, MM / 128), 256, GEMM_SMEM>>>(
        ahi, alo, w2hi, w2lo, b2, out, DD);
}

// round 4
// speedup vs baseline: 3.0296x; 2.1209x over previous
#include <cuda_runtime.h>
#include <cuda_bf16.h>
#include <math.h>
#include <stdint.h>

#define BB 2
#define SS 2048
#define DD 1024
#define HH 16
#define HDD 64
#define MM (BB*SS)          // 4096
#define KK DD               // 1024

// ---------------- device scratch (no runtime allocation allowed) ----------------
__device__ float g_qkv[(size_t)MM * 3 * DD];          // fp32 qkv
__device__ __nv_bfloat16 g_xhi[(size_t)MM * KK];
__device__ __nv_bfloat16 g_xlo[(size_t)MM * KK];
__device__ __nv_bfloat16 g_w1hi[(size_t)3 * DD * KK]; // transposed [3D, K]
__device__ __nv_bfloat16 g_w1lo[(size_t)3 * DD * KK];
__device__ __nv_bfloat16 g_w2hi[(size_t)DD * KK];     // transposed [D, K]
__device__ __nv_bfloat16 g_w2lo[(size_t)DD * KK];
__device__ __nv_bfloat16 g_ahi[(size_t)MM * DD];      // attention out hi
__device__ __nv_bfloat16 g_alo[(size_t)MM * DD];      // attention out lo

// ---------------- PTX helpers (base sm_80+ ISA only) ----------
__device__ __forceinline__ uint32_t smem_u32(const void* p) {
    uint32_t a;
    asm("{ .reg .u64 t; cvta.to.shared.u64 t, %1; cvt.u32.u64 %0, t; }" : "=r"(a) : "l"(p));
    return a;
}
__device__ __forceinline__ void cp16(uint32_t dst, const void* src) {
    asm volatile("cp.async.cg.shared.global [%0], [%1], 16;" :: "r"(dst), "l"(src));
}
__device__ __forceinline__ void cp_commit() {
    asm volatile("cp.async.commit_group;" ::: "memory");
}
template <int N>
__device__ __forceinline__ void cp_wait() {
    asm volatile("cp.async.wait_group %0;" :: "n"(N) : "memory");
}
__device__ __forceinline__ void ldsm4(uint32_t* r, uint32_t addr) {
    asm volatile("ldmatrix.sync.aligned.m8n8.x4.shared.b16 {%0,%1,%2,%3}, [%4];"
                 : "=r"(r[0]), "=r"(r[1]), "=r"(r[2]), "=r"(r[3]) : "r"(addr));
}
__device__ __forceinline__ void ldsm4t(uint32_t* r, uint32_t addr) {
    asm volatile("ldmatrix.sync.aligned.m8n8.x4.trans.shared.b16 {%0,%1,%2,%3}, [%4];"
                 : "=r"(r[0]), "=r"(r[1]), "=r"(r[2]), "=r"(r[3]) : "r"(addr));
}
__device__ __forceinline__ void mma16816(float* d, const uint32_t* a, const uint32_t* b) {
    asm volatile(
        "mma.sync.aligned.m16n8k16.row.col.f32.bf16.bf16.f32 "
        "{%0,%1,%2,%3}, {%4,%5,%6,%7}, {%8,%9}, {%0,%1,%2,%3};"
        : "+f"(d[0]), "+f"(d[1]), "+f"(d[2]), "+f"(d[3])
        : "r"(a[0]), "r"(a[1]), "r"(a[2]), "r"(a[3]), "r"(b[0]), "r"(b[1]));
}
__device__ __forceinline__ void mma2(float* d, const uint32_t* a, uint32_t b0, uint32_t b1) {
    asm volatile(
        "mma.sync.aligned.m16n8k16.row.col.f32.bf16.bf16.f32 "
        "{%0,%1,%2,%3}, {%4,%5,%6,%7}, {%8,%9}, {%0,%1,%2,%3};"
        : "+f"(d[0]), "+f"(d[1]), "+f"(d[2]), "+f"(d[3])
        : "r"(a[0]), "r"(a[1]), "r"(a[2]), "r"(a[3]), "r"(b0), "r"(b1));
}
// pack two f32 -> bf16x2 (lo half = first arg)
__device__ __forceinline__ uint32_t pk2(float lo_, float hi_) {
    uint32_t r;
    asm("cvt.rn.bf16x2.f32 %0, %1, %2;" : "=r"(r) : "f"(hi_), "f"(lo_));
    return r;
}
// hi/lo split of a pair -> packed bf16x2 hi and lo
__device__ __forceinline__ void split2(float a, float b, uint32_t& hi, uint32_t& lo) {
    hi = pk2(a, b);
    float fa = __uint_as_float(hi << 16);
    float fb = __uint_as_float(hi & 0xffff0000u);
    lo = pk2(a - fa, b - fb);
}

// ========================== GEMM (unchanged from R3) ==========================
__device__ __forceinline__ uint32_t swz(int row, int c) {
    return (uint32_t)(row * 64 + ((c ^ ((row >> 1) & 3)) << 4));
}
#define TILE_BYTES 8192
#define STAGE_BYTES (4 * TILE_BYTES)
#define GEMM_SMEM  (2 * STAGE_BYTES)   // 64 KB

__global__ void __launch_bounds__(256, 1) gemm_mma(
    const __nv_bfloat16* __restrict__ Ahi, const __nv_bfloat16* __restrict__ Alo,
    const __nv_bfloat16* __restrict__ Bhi, const __nv_bfloat16* __restrict__ Blo,
    const float* __restrict__ bias, float* __restrict__ C, int N)
{
    extern __shared__ char smem[];
    const uint32_t sbase = smem_u32(smem);
    const int tid  = threadIdx.x;
    const int wid  = tid >> 5;
    const int lane = tid & 31;
    const int wm = (wid >> 2) * 64;
    const int wn = (wid & 3) * 32;
    const int m0 = blockIdx.y << 7;
    const int n0 = blockIdx.x << 7;

    const __nv_bfloat16* srcs[4] = {
        Ahi + (size_t)m0 * KK, Alo + (size_t)m0 * KK,
        Bhi + (size_t)n0 * KK, Blo + (size_t)n0 * KK };

    auto prefetch = [&](int kt, int s) {
        uint32_t stb = sbase + s * STAGE_BYTES;
#pragma unroll
        for (int t = 0; t < 4; t++) {
            const __nv_bfloat16* g = srcs[t] + kt * 32;
#pragma unroll
            for (int i = 0; i < 2; i++) {
                int cid = i * 256 + tid;
                int row = cid >> 2, c = cid & 3;
                cp16(stb + t * TILE_BYTES + swz(row, c),
                     g + (size_t)row * KK + c * 8);
            }
        }
    };

    float acc[4][4][4];
#pragma unroll
    for (int i = 0; i < 4; i++)
#pragma unroll
        for (int j = 0; j < 4; j++)
#pragma unroll
            for (int k = 0; k < 4; k++) acc[i][j][k] = 0.f;

    prefetch(0, 0);
    cp_commit();

    const int KCH = KK / 32;
    for (int kt = 0; kt < KCH; kt++) {
        const int s = kt & 1;
        if (kt + 1 < KCH) {
            prefetch(kt + 1, s ^ 1);
            cp_commit();
            cp_wait<1>();
        } else {
            cp_wait<0>();
        }
        __syncthreads();

        const uint32_t ahb = sbase + s * STAGE_BYTES;
        const uint32_t alb = ahb + TILE_BYTES;
        const uint32_t bhb = ahb + 2 * TILE_BYTES;
        const uint32_t blb = ahb + 3 * TILE_BYTES;

#pragma unroll
        for (int kh = 0; kh < 2; kh++) {
            const int lrow = lane & 15;
            const int lkc  = kh * 2 + (lane >> 4);

            uint32_t ah[4][4], al[4][4];
#pragma unroll
            for (int mt = 0; mt < 4; mt++) {
                uint32_t off = swz(wm + mt * 16 + lrow, lkc);
                ldsm4(ah[mt], ahb + off);
                ldsm4(al[mt], alb + off);
            }
            uint32_t bh[4][2], bl[4][2];
#pragma unroll
            for (int np = 0; np < 2; np++) {
                uint32_t off = swz(wn + np * 16 + lrow, lkc);
                uint32_t r[4];
                ldsm4(r, bhb + off);
                bh[np * 2][0] = r[0]; bh[np * 2][1] = r[2];
                bh[np * 2 + 1][0] = r[1]; bh[np * 2 + 1][1] = r[3];
                ldsm4(r, blb + off);
                bl[np * 2][0] = r[0]; bl[np * 2][1] = r[2];
                bl[np * 2 + 1][0] = r[1]; bl[np * 2 + 1][1] = r[3];
            }
#pragma unroll
            for (int mt = 0; mt < 4; mt++)
#pragma unroll
                for (int nt = 0; nt < 4; nt++) {
                    mma16816(acc[mt][nt], ah[mt], bh[nt]);
                    mma16816(acc[mt][nt], ah[mt], bl[nt]);
                    mma16816(acc[mt][nt], al[mt], bh[nt]);
                }
        }
        __syncthreads();
    }

#pragma unroll
    for (int mt = 0; mt < 4; mt++) {
#pragma unroll
        for (int nt = 0; nt < 4; nt++) {
            int row = m0 + wm + mt * 16 + (lane >> 2);
            int col = n0 + wn + nt * 8 + ((lane & 3) << 1);
            float b0 = __ldg(bias + col), b1 = __ldg(bias + col + 1);
            float* d = acc[mt][nt];
            *(float2*)(C + (size_t)row * N + col) =
                make_float2(d[0] + b0, d[1] + b1);
            *(float2*)(C + (size_t)(row + 8) * N + col) =
                make_float2(d[2] + b0, d[3] + b1);
        }
    }
}

// ========================== prep kernels (unchanged) ==========================
__global__ void split_f32(const float* __restrict__ in,
                          __nv_bfloat16* __restrict__ hi,
                          __nv_bfloat16* __restrict__ lo, int n4)
{
    int i = blockIdx.x * blockDim.x + threadIdx.x;
    if (i >= n4) return;
    float4 v = ((const float4*)in)[i];
    uint32_t h0, l0, h1, l1;
    split2(v.x, v.y, h0, l0);
    split2(v.z, v.w, h1, l1);
    ((uint2*)hi)[i] = make_uint2(h0, h1);
    ((uint2*)lo)[i] = make_uint2(l0, l1);
}

__global__ void transpose_split(const float* __restrict__ in,
                                __nv_bfloat16* __restrict__ hi,
                                __nv_bfloat16* __restrict__ lo, int K, int N)
{
    __shared__ float t[32][33];
    int bx = blockIdx.x << 5;
    int by = blockIdx.y << 5;
    int tx = threadIdx.x, ty = threadIdx.y;
#pragma unroll
    for (int i = 0; i < 32; i += 8)
        t[ty + i][tx] = in[(size_t)(by + ty + i) * N + bx + tx];
    __syncthreads();
#pragma unroll
    for (int i = 0; i < 32; i += 8) {
        float v = t[tx][ty + i];
        int n = bx + ty + i, k = by + tx;
        __nv_bfloat16 h = __float2bfloat16(v);
        hi[(size_t)n * K + k] = h;
        lo[(size_t)n * K + k] = __float2bfloat16(v - __bfloat162float(h));
    }
}

// ========================== tensor-core flash attention ==========================
// 128B-row tile swizzle: chunk c (16B) of row r -> c ^ (r & 7)
__device__ __forceinline__ uint32_t taddr(uint32_t base, int row, int chunk) {
    return base + (uint32_t)(row * 128) + (uint32_t)((chunk ^ (row & 7)) << 4);
}

#define FL_SMEM 65536
// offsets: QH 0 (16K), QL 16K, KH 32K (8K), KL 40K, VH 48K, VL 56K

__global__ void __launch_bounds__(256, 2) flash_attn_tc(
    const float* __restrict__ qkv,
    __nv_bfloat16* __restrict__ out_hi, __nv_bfloat16* __restrict__ out_lo)
{
    extern __shared__ char sm[];
    const uint32_t sQH = smem_u32(sm);
    const uint32_t sQL = sQH + 16384;
    const uint32_t sKH = sQH + 32768;
    const uint32_t sKL = sQH + 40960;
    const uint32_t sVH = sQH + 49152;
    const uint32_t sVL = sQH + 57344;
    char* smp = sm;   // generic-pointer view for stores

    const int tid  = threadIdx.x;
    const int wid  = tid >> 5;
    const int lane = tid & 31;
    const int lrow = lane & 15;
    const int wm   = wid << 4;                 // warp rows [wm, wm+16)
    const int qt   = (gridDim.x - 1) - blockIdx.x;   // heavy tiles first
    const int h    = blockIdx.y;
    const int b    = blockIdx.z;
    const int q0   = qt << 7;                  // 128 q-rows per CTA
    const size_t rstride = 3 * DD;

    // ---- load Q (scaled by 1/8), split hi/lo into smem ----
    {
        int r  = tid >> 1;                 // 0..127
        int cb = (tid & 1) << 5;           // 0 or 32
        const float* qp = qkv + (size_t)(b * SS + q0 + r) * rstride + h * HDD + cb;
#pragma unroll
        for (int i = 0; i < 8; i++) {
            float4 v = *(const float4*)(qp + i * 4);
            int c = cb + i * 4;
            uint32_t a = (uint32_t)(r * 128 + (((c >> 3) ^ (r & 7)) << 4) + ((c & 7) << 1));
            uint32_t h0, l0, h1, l1;
            split2(v.x * 0.125f, v.y * 0.125f, h0, l0);
            split2(v.z * 0.125f, v.w * 0.125f, h1, l1);
            *(uint2*)(smp + a)         = make_uint2(h0, h1);
            *(uint2*)(smp + 16384 + a) = make_uint2(l0, l1);
        }
    }

    float o[8][4];
#pragma unroll
    for (int nt = 0; nt < 8; nt++)
#pragma unroll
        for (int k = 0; k < 4; k++) o[nt][k] = 0.f;
    float m0r = -INFINITY, m1r = -INFINITY, l0r = 0.f, l1r = 0.f;

    const int grow0 = q0 + wm + (lane >> 2);
    const int grow1 = grow0 + 8;
    const int nkt = 2 * qt + 2;               // k-tiles of 64

    for (int kt = 0; kt < nkt; kt++) {
        const int k0 = kt << 6;
        __syncthreads();   // previous iteration's reads of K/V done (covers Q on iter 0)

        // ---- load K,V tiles (64x64), split hi/lo ----
        {
            int r  = tid >> 2;                // 0..63
            int cb = (tid & 3) << 4;          // 0,16,32,48
            const float* kp = qkv + (size_t)(b * SS + k0 + r) * rstride + DD + h * HDD + cb;
#pragma unroll
            for (int i = 0; i < 4; i++) {
                int c = cb + i * 4;
                uint32_t a = (uint32_t)(r * 128 + (((c >> 3) ^ (r & 7)) << 4) + ((c & 7) << 1));
                float4 kv = *(const float4*)(kp + i * 4);
                float4 vv = *(const float4*)(kp + DD + i * 4);
                uint32_t h0, l0, h1, l1;
                split2(kv.x, kv.y, h0, l0);
                split2(kv.z, kv.w, h1, l1);
                *(uint2*)(smp + 32768 + a) = make_uint2(h0, h1);
                *(uint2*)(smp + 40960 + a) = make_uint2(l0, l1);
                split2(vv.x, vv.y, h0, l0);
                split2(vv.z, vv.w, h1, l1);
                *(uint2*)(smp + 49152 + a) = make_uint2(h0, h1);
                *(uint2*)(smp + 57344 + a) = make_uint2(l0, l1);
            }
        }
        __syncthreads();

        // ---- S = Q K^T (bf16x3) ----
        float s[8][4];
#pragma unroll
        for (int nt = 0; nt < 8; nt++)
#pragma unroll
            for (int k = 0; k < 4; k++) s[nt][k] = 0.f;

#pragma unroll
        for (int ks = 0; ks < 4; ks++) {
            const int ck = ks * 2 + (lane >> 4);
            uint32_t qh[4], ql[4];
            ldsm4(qh, taddr(sQH, wm + lrow, ck));
            ldsm4(ql, taddr(sQL, wm + lrow, ck));
#pragma unroll
            for (int np = 0; np < 4; np++) {
                uint32_t rh[4], rl[4];
                ldsm4(rh, taddr(sKH, np * 16 + lrow, ck));
                ldsm4(rl, taddr(sKL, np * 16 + lrow, ck));
                mma2(s[2 * np],     qh, rh[0], rh[2]);
                mma2(s[2 * np],     ql, rh[0], rh[2]);
                mma2(s[2 * np],     qh, rl[0], rl[2]);
                mma2(s[2 * np + 1], qh, rh[1], rh[3]);
                mma2(s[2 * np + 1], ql, rh[1], rh[3]);
                mma2(s[2 * np + 1], qh, rl[1], rl[3]);
            }
        }

        // ---- causal mask (only near-diagonal tiles) ----
        if (k0 + 63 > grow0) {
#pragma unroll
            for (int nt = 0; nt < 8; nt++) {
                int col = k0 + nt * 8 + ((lane & 3) << 1);
                if (col > grow0)     s[nt][0] = -1e30f;
                if (col + 1 > grow0) s[nt][1] = -1e30f;
                if (col > grow1)     s[nt][2] = -1e30f;
                if (col + 1 > grow1) s[nt][3] = -1e30f;
            }
        }

        // ---- online softmax (rows grow0, grow1) ----
        float ml0 = -INFINITY, ml1 = -INFINITY;
#pragma unroll
        for (int nt = 0; nt < 8; nt++) {
            ml0 = fmaxf(ml0, fmaxf(s[nt][0], s[nt][1]));
            ml1 = fmaxf(ml1, fmaxf(s[nt][2], s[nt][3]));
        }
        ml0 = fmaxf(ml0, __shfl_xor_sync(0xffffffffu, ml0, 1));
        ml0 = fmaxf(ml0, __shfl_xor_sync(0xffffffffu, ml0, 2));
        ml1 = fmaxf(ml1, __shfl_xor_sync(0xffffffffu, ml1, 1));
        ml1 = fmaxf(ml1, __shfl_xor_sync(0xffffffffu, ml1, 2));
        float mn0 = fmaxf(m0r, ml0), mn1 = fmaxf(m1r, ml1);
        float c0 = __expf(m0r - mn0), c1 = __expf(m1r - mn1);
        m0r = mn0; m1r = mn1;
        float rs0 = 0.f, rs1 = 0.f;
#pragma unroll
        for (int nt = 0; nt < 8; nt++) {
            s[nt][0] = __expf(s[nt][0] - mn0);
            s[nt][1] = __expf(s[nt][1] - mn0);
            s[nt][2] = __expf(s[nt][2] - mn1);
            s[nt][3] = __expf(s[nt][3] - mn1);
            rs0 += s[nt][0] + s[nt][1];
            rs1 += s[nt][2] + s[nt][3];
        }
        rs0 += __shfl_xor_sync(0xffffffffu, rs0, 1);
        rs0 += __shfl_xor_sync(0xffffffffu, rs0, 2);
        rs1 += __shfl_xor_sync(0xffffffffu, rs1, 1);
        rs1 += __shfl_xor_sync(0xffffffffu, rs1, 2);
        l0r = l0r * c0 + rs0;
        l1r = l1r * c1 + rs1;
#pragma unroll
        for (int nt = 0; nt < 8; nt++) {
            o[nt][0] *= c0; o[nt][1] *= c0;
            o[nt][2] *= c1; o[nt][3] *= c1;
        }

        // ---- O += P V  (P from S-fragments, V via ldmatrix.trans) ----
#pragma unroll
        for (int j = 0; j < 4; j++) {           // k-slices over kpos (16 each)
            uint32_t aPh[4], aPl[4];
            split2(s[2 * j][0],     s[2 * j][1],     aPh[0], aPl[0]);
            split2(s[2 * j][2],     s[2 * j][3],     aPh[1], aPl[1]);
            split2(s[2 * j + 1][0], s[2 * j + 1][1], aPh[2], aPl[2]);
            split2(s[2 * j + 1][2], s[2 * j + 1][3], aPh[3], aPl[3]);
#pragma unroll
            for (int ci = 0; ci < 4; ci++) {    // hd chunk pairs
                const int ck = ci * 2 + (lane >> 4);
                uint32_t rvh[4], rvl[4];
                ldsm4t(rvh, taddr(sVH, j * 16 + lrow, ck));
                ldsm4t(rvl, taddr(sVL, j * 16 + lrow, ck));
                mma2(o[2 * ci],     aPh, rvh[0], rvh[1]);
                mma2(o[2 * ci],     aPl, rvh[0], rvh[1]);
                mma2(o[2 * ci],     aPh, rvl[0], rvl[1]);
                mma2(o[2 * ci + 1], aPh, rvh[2], rvh[3]);
                mma2(o[2 * ci + 1], aPl, rvh[2], rvh[3]);
                mma2(o[2 * ci + 1], aPh, rvl[2], rvl[3]);
            }
        }
    }

    // ---- epilogue: normalize, split hi/lo, store merged-head [B*S, D] ----
    float inv0 = 1.f / l0r, inv1 = 1.f / l1r;
    size_t r0 = (size_t)(b * SS + grow0 - wm + wm) * DD;  // = (b*SS+grow0)*DD
    r0 = (size_t)(b * SS + grow0) * DD;
    size_t r1 = (size_t)(b * SS + grow1) * DD;
    int colb = h * HDD + ((lane & 3) << 1);
#pragma unroll
    for (int nt = 0; nt < 8; nt++) {
        int col = colb + nt * 8;
        uint32_t hp, lp;
        split2(o[nt][0] * inv0, o[nt][1] * inv0, hp, lp);
        *(uint32_t*)(out_hi + r0 + col) = hp;
        *(uint32_t*)(out_lo + r0 + col) = lp;
        split2(o[nt][2] * inv1, o[nt][3] * inv1, hp, lp);
        *(uint32_t*)(out_hi + r1 + col) = hp;
        *(uint32_t*)(out_lo + r1 + col) = lp;
    }
}

// ---------------------------------------------------------------------------
extern "C" void kernel_launch(void* const* d_in, const int* in_sizes, int n_in,
                              void* d_out, int out_size)
{
    const float* x  = (const float*)d_in[0];
    const float* w1 = (const float*)d_in[1];
    const float* b1 = (const float*)d_in[2];
    const float* w2 = (const float*)d_in[3];
    const float* b2 = (const float*)d_in[4];
    float* out = (float*)d_out;

    float* qkv; __nv_bfloat16 *xhi, *xlo, *w1hi, *w1lo, *w2hi, *w2lo, *ahi, *alo;
    cudaGetSymbolAddress((void**)&qkv,  g_qkv);
    cudaGetSymbolAddress((void**)&xhi,  g_xhi);
    cudaGetSymbolAddress((void**)&xlo,  g_xlo);
    cudaGetSymbolAddress((void**)&w1hi, g_w1hi);
    cudaGetSymbolAddress((void**)&w1lo, g_w1lo);
    cudaGetSymbolAddress((void**)&w2hi, g_w2hi);
    cudaGetSymbolAddress((void**)&w2lo, g_w2lo);
    cudaGetSymbolAddress((void**)&ahi,  g_ahi);
    cudaGetSymbolAddress((void**)&alo,  g_alo);

    static int inited = 0;
    if (!inited) {
        cudaFuncSetAttribute(gemm_mma,
            cudaFuncAttributeMaxDynamicSharedMemorySize, GEMM_SMEM);
        cudaFuncSetAttribute(flash_attn_tc,
            cudaFuncAttributeMaxDynamicSharedMemorySize, FL_SMEM);
        inited = 1;
    }

    // 0) operand prep
    split_f32<<<(MM * KK / 4 + 255) / 256, 256>>>(x, xhi, xlo, MM * KK / 4);
    transpose_split<<<dim3(3 * DD / 32, KK / 32), dim3(32, 8)>>>(w1, w1hi, w1lo, KK, 3 * DD);
    transpose_split<<<dim3(DD / 32, KK / 32), dim3(32, 8)>>>(w2, w2hi, w2lo, KK, DD);

    // 1) QKV projection (tensor cores)
    gemm_mma<<<dim3(3 * DD / 128, MM / 128), 256, GEMM_SMEM>>>(
        xhi, xlo, w1hi, w1lo, b1, qkv, 3 * DD);

    // 2) causal flash attention on tensor cores
    flash_attn_tc<<<dim3(SS / 128, HH, BB), 256, FL_SMEM>>>(qkv, ahi, alo);

    // 3) output projection (tensor cores)
    gemm_mma<<<dim3(DD / 128, MM / 128), 256, GEMM_SMEM>>>(
        ahi, alo, w2hi, w2lo, b2, out, DD);
}

// round 5
// speedup vs baseline: 3.2899x; 1.0859x over previous
#include <cuda_runtime.h>
#include <cuda_bf16.h>
#include <math.h>
#include <stdint.h>

#define BB 2
#define SS 2048
#define DD 1024
#define HH 16
#define HDD 64
#define MM (BB*SS)          // 4096
#define KK DD               // 1024

// ---------------- device scratch (no runtime allocation allowed) ----------------
__device__ float g_qkv[(size_t)MM * 3 * DD];          // fp32 qkv
__device__ __nv_bfloat16 g_xhi[(size_t)MM * KK];
__device__ __nv_bfloat16 g_xlo[(size_t)MM * KK];
__device__ __nv_bfloat16 g_w1hi[(size_t)3 * DD * KK]; // transposed [3D, K]
__device__ __nv_bfloat16 g_w1lo[(size_t)3 * DD * KK];
__device__ __nv_bfloat16 g_w2hi[(size_t)DD * KK];     // transposed [D, K]
__device__ __nv_bfloat16 g_w2lo[(size_t)DD * KK];
__device__ __nv_bfloat16 g_ahi[(size_t)MM * DD];      // attention out hi
__device__ __nv_bfloat16 g_alo[(size_t)MM * DD];      // attention out lo
__device__ __nv_bfloat16 g_khi[(size_t)MM * DD];      // pre-split K/V for flash
__device__ __nv_bfloat16 g_klo[(size_t)MM * DD];
__device__ __nv_bfloat16 g_vhi[(size_t)MM * DD];
__device__ __nv_bfloat16 g_vlo[(size_t)MM * DD];

// ---------------- PTX helpers (base sm_80+ ISA only) ----------
__device__ __forceinline__ uint32_t smem_u32(const void* p) {
    uint32_t a;
    asm("{ .reg .u64 t; cvta.to.shared.u64 t, %1; cvt.u32.u64 %0, t; }" : "=r"(a) : "l"(p));
    return a;
}
__device__ __forceinline__ void cp16(uint32_t dst, const void* src) {
    asm volatile("cp.async.cg.shared.global [%0], [%1], 16;" :: "r"(dst), "l"(src));
}
__device__ __forceinline__ void cp_commit() {
    asm volatile("cp.async.commit_group;" ::: "memory");
}
template <int N>
__device__ __forceinline__ void cp_wait() {
    asm volatile("cp.async.wait_group %0;" :: "n"(N) : "memory");
}
__device__ __forceinline__ void ldsm4(uint32_t* r, uint32_t addr) {
    asm volatile("ldmatrix.sync.aligned.m8n8.x4.shared.b16 {%0,%1,%2,%3}, [%4];"
                 : "=r"(r[0]), "=r"(r[1]), "=r"(r[2]), "=r"(r[3]) : "r"(addr));
}
__device__ __forceinline__ void ldsm4t(uint32_t* r, uint32_t addr) {
    asm volatile("ldmatrix.sync.aligned.m8n8.x4.trans.shared.b16 {%0,%1,%2,%3}, [%4];"
                 : "=r"(r[0]), "=r"(r[1]), "=r"(r[2]), "=r"(r[3]) : "r"(addr));
}
__device__ __forceinline__ void mma2(float* d, const uint32_t* a, uint32_t b0, uint32_t b1) {
    asm volatile(
        "mma.sync.aligned.m16n8k16.row.col.f32.bf16.bf16.f32 "
        "{%0,%1,%2,%3}, {%4,%5,%6,%7}, {%8,%9}, {%0,%1,%2,%3};"
        : "+f"(d[0]), "+f"(d[1]), "+f"(d[2]), "+f"(d[3])
        : "r"(a[0]), "r"(a[1]), "r"(a[2]), "r"(a[3]), "r"(b0), "r"(b1));
}
__device__ __forceinline__ uint32_t pk2(float lo_, float hi_) {
    uint32_t r;
    asm("cvt.rn.bf16x2.f32 %0, %1, %2;" : "=r"(r) : "f"(hi_), "f"(lo_));
    return r;
}
__device__ __forceinline__ void split2(float a, float b, uint32_t& hi, uint32_t& lo) {
    hi = pk2(a, b);
    float fa = __uint_as_float(hi << 16);
    float fb = __uint_as_float(hi & 0xffff0000u);
    lo = pk2(a - fa, b - fb);
}

// ========================== GEMM ==========================
__device__ __forceinline__ uint32_t swz(int row, int c) {
    return (uint32_t)(row * 64 + ((c ^ ((row >> 1) & 3)) << 4));
}
#define TILE_BYTES 8192
#define STAGE_BYTES (4 * TILE_BYTES)
#define GEMM_SMEM  (3 * STAGE_BYTES)   // 96 KB, 3 stages

__global__ void __launch_bounds__(256, 2) gemm_mma(
    const __nv_bfloat16* __restrict__ Ahi, const __nv_bfloat16* __restrict__ Alo,
    const __nv_bfloat16* __restrict__ Bhi, const __nv_bfloat16* __restrict__ Blo,
    const float* __restrict__ bias, float* __restrict__ C, int N)
{
    extern __shared__ char smem[];
    const uint32_t sbase = smem_u32(smem);
    const int tid  = threadIdx.x;
    const int wid  = tid >> 5;
    const int lane = tid & 31;
    const int wm = (wid >> 2) * 64;
    const int wn = (wid & 3) * 32;
    const int m0 = blockIdx.y << 7;
    const int n0 = blockIdx.x << 7;

    const __nv_bfloat16* srcs[4] = {
        Ahi + (size_t)m0 * KK, Alo + (size_t)m0 * KK,
        Bhi + (size_t)n0 * KK, Blo + (size_t)n0 * KK };

    auto prefetch = [&](int kt, int s) {
        uint32_t stb = sbase + s * STAGE_BYTES;
#pragma unroll
        for (int t = 0; t < 4; t++) {
            const __nv_bfloat16* g = srcs[t] + kt * 32;
#pragma unroll
            for (int i = 0; i < 2; i++) {
                int cid = i * 256 + tid;
                int row = cid >> 2, c = cid & 3;
                cp16(stb + t * TILE_BYTES + swz(row, c),
                     g + (size_t)row * KK + c * 8);
            }
        }
    };

    float acc[4][4][4];
#pragma unroll
    for (int i = 0; i < 4; i++)
#pragma unroll
        for (int j = 0; j < 4; j++)
#pragma unroll
            for (int k = 0; k < 4; k++) acc[i][j][k] = 0.f;

    prefetch(0, 0); cp_commit();
    prefetch(1, 1); cp_commit();

    const int KCH = KK / 32;   // 32
    for (int kt = 0; kt < KCH; kt++) {
        const int s = kt % 3;
        if (kt == KCH - 1) cp_wait<0>(); else cp_wait<1>();
        __syncthreads();

        const uint32_t ahb = sbase + s * STAGE_BYTES;
        const uint32_t alb = ahb + TILE_BYTES;
        const uint32_t bhb = ahb + 2 * TILE_BYTES;
        const uint32_t blb = ahb + 3 * TILE_BYTES;

#pragma unroll
        for (int kh = 0; kh < 2; kh++) {
            const int lrow = lane & 15;
            const int lkc  = kh * 2 + (lane >> 4);

            uint32_t ah[4][4], al[4][4];
#pragma unroll
            for (int mt = 0; mt < 4; mt++) {
                uint32_t off = swz(wm + mt * 16 + lrow, lkc);
                ldsm4(ah[mt], ahb + off);
                ldsm4(al[mt], alb + off);
            }
#pragma unroll
            for (int nh = 0; nh < 2; nh++) {
                uint32_t off = swz(wn + nh * 16 + lrow, lkc);
                uint32_t rbh[4], rbl[4];
                ldsm4(rbh, bhb + off);
                ldsm4(rbl, blb + off);
                const int nb = nh * 2;
                // pass 1: Ah * Bh (8 independent MMAs)
#pragma unroll
                for (int mt = 0; mt < 4; mt++) {
                    mma2(acc[mt][nb],     ah[mt], rbh[0], rbh[2]);
                    mma2(acc[mt][nb + 1], ah[mt], rbh[1], rbh[3]);
                }
                // pass 2: Ah * Bl
#pragma unroll
                for (int mt = 0; mt < 4; mt++) {
                    mma2(acc[mt][nb],     ah[mt], rbl[0], rbl[2]);
                    mma2(acc[mt][nb + 1], ah[mt], rbl[1], rbl[3]);
                }
                // pass 3: Al * Bh
#pragma unroll
                for (int mt = 0; mt < 4; mt++) {
                    mma2(acc[mt][nb],     al[mt], rbh[0], rbh[2]);
                    mma2(acc[mt][nb + 1], al[mt], rbh[1], rbh[3]);
                }
            }
        }
        __syncthreads();
        if (kt + 2 < KCH) { prefetch(kt + 2, (kt + 2) % 3); cp_commit(); }
    }

#pragma unroll
    for (int mt = 0; mt < 4; mt++) {
#pragma unroll
        for (int nt = 0; nt < 4; nt++) {
            int row = m0 + wm + mt * 16 + (lane >> 2);
            int col = n0 + wn + nt * 8 + ((lane & 3) << 1);
            float b0 = __ldg(bias + col), b1 = __ldg(bias + col + 1);
            float* d = acc[mt][nt];
            *(float2*)(C + (size_t)row * N + col) =
                make_float2(d[0] + b0, d[1] + b1);
            *(float2*)(C + (size_t)(row + 8) * N + col) =
                make_float2(d[2] + b0, d[3] + b1);
        }
    }
}

// ========================== prep kernels ==========================
__global__ void split_f32(const float* __restrict__ in,
                          __nv_bfloat16* __restrict__ hi,
                          __nv_bfloat16* __restrict__ lo, int n4)
{
    int i = blockIdx.x * blockDim.x + threadIdx.x;
    if (i >= n4) return;
    float4 v = ((const float4*)in)[i];
    uint32_t h0, l0, h1, l1;
    split2(v.x, v.y, h0, l0);
    split2(v.z, v.w, h1, l1);
    ((uint2*)hi)[i] = make_uint2(h0, h1);
    ((uint2*)lo)[i] = make_uint2(l0, l1);
}

__global__ void transpose_split(const float* __restrict__ in,
                                __nv_bfloat16* __restrict__ hi,
                                __nv_bfloat16* __restrict__ lo, int K, int N)
{
    __shared__ float t[32][33];
    int bx = blockIdx.x << 5;
    int by = blockIdx.y << 5;
    int tx = threadIdx.x, ty = threadIdx.y;
#pragma unroll
    for (int i = 0; i < 32; i += 8)
        t[ty + i][tx] = in[(size_t)(by + ty + i) * N + bx + tx];
    __syncthreads();
#pragma unroll
    for (int i = 0; i < 32; i += 8) {
        float v = t[tx][ty + i];
        int n = bx + ty + i, k = by + tx;
        __nv_bfloat16 h = __float2bfloat16(v);
        hi[(size_t)n * K + k] = h;
        lo[(size_t)n * K + k] = __float2bfloat16(v - __bfloat162float(h));
    }
}

// Split K and V sections of qkv into bf16 hi/lo [B*S, D] arrays (row = 3*64
// bf16 slices per head; a (row, head) slice is exactly 128 B = one smem row).
__global__ void kv_split(const float* __restrict__ qkv,
                         __nv_bfloat16* __restrict__ khi, __nv_bfloat16* __restrict__ klo,
                         __nv_bfloat16* __restrict__ vhi, __nv_bfloat16* __restrict__ vlo)
{
    int i = blockIdx.x * blockDim.x + threadIdx.x;
    if (i >= MM * DD / 4) return;
    int row = i >> 8;            // DD/4 = 256
    int c4  = (i & 255) << 2;
    const float* base = qkv + (size_t)row * 3 * DD + c4;
    float4 kv = *(const float4*)(base + DD);
    float4 vv = *(const float4*)(base + 2 * DD);
    uint32_t h0, l0, h1, l1;
    split2(kv.x, kv.y, h0, l0);
    split2(kv.z, kv.w, h1, l1);
    ((uint2*)khi)[i] = make_uint2(h0, h1);
    ((uint2*)klo)[i] = make_uint2(l0, l1);
    split2(vv.x, vv.y, h0, l0);
    split2(vv.z, vv.w, h1, l1);
    ((uint2*)vhi)[i] = make_uint2(h0, h1);
    ((uint2*)vlo)[i] = make_uint2(l0, l1);
}

// ========================== tensor-core flash attention ==========================
__device__ __forceinline__ uint32_t taddr(uint32_t base, int row, int chunk) {
    return base + (uint32_t)(row * 128) + (uint32_t)((chunk ^ (row & 7)) << 4);
}

#define FL_SMEM 98304
// layout: QH 0 (16K), QL 16K, then 2 stages of 32K: {KH 8K, KL 8K, VH 8K, VL 8K}

__global__ void __launch_bounds__(256, 2) flash_attn_tc(
    const float* __restrict__ qkv,
    const __nv_bfloat16* __restrict__ khi, const __nv_bfloat16* __restrict__ klo,
    const __nv_bfloat16* __restrict__ vhi, const __nv_bfloat16* __restrict__ vlo,
    __nv_bfloat16* __restrict__ out_hi, __nv_bfloat16* __restrict__ out_lo)
{
    extern __shared__ char sm[];
    const uint32_t sQH = smem_u32(sm);
    const uint32_t sQL = sQH + 16384;
    const uint32_t sKV = sQH + 32768;
    char* smp = sm;

    const int tid  = threadIdx.x;
    const int wid  = tid >> 5;
    const int lane = tid & 31;
    const int lrow = lane & 15;
    const int wm   = wid << 4;
    const int qt   = (gridDim.x - 1) - blockIdx.x;   // heavy tiles first
    const int h    = blockIdx.y;
    const int b    = blockIdx.z;
    const int q0   = qt << 7;
    const size_t rstride = 3 * DD;

    // ---- K/V prefetch (cp.async, pre-split bf16, swizzled rows) ----
    auto pf = [&](int kt, int st) {
        uint32_t sb = sKV + st * 32768;
        const size_t goff = (size_t)(b * SS + (kt << 6)) * DD + h * HDD;
#pragma unroll
        for (int t = 0; t < 8; t++) {
            const __nv_bfloat16* gp = (t < 2) ? khi : (t < 4) ? klo
                                    : (t < 6) ? vhi : vlo;
            int cid = ((t & 1) << 8) + tid;     // 0..511
            int row = cid >> 3, c = cid & 7;
            cp16(sb + (uint32_t)((t >> 1) * 8192 + row * 128 + ((c ^ (row & 7)) << 4)),
                 gp + goff + (size_t)row * DD + c * 8);
        }
    };

    pf(0, 0); cp_commit();

    // ---- load Q (scaled by 1/8), split hi/lo into smem ----
    {
        int r  = tid >> 1;
        int cb = (tid & 1) << 5;
        const float* qp = qkv + (size_t)(b * SS + q0 + r) * rstride + h * HDD + cb;
#pragma unroll
        for (int i = 0; i < 8; i++) {
            float4 v = *(const float4*)(qp + i * 4);
            int c = cb + i * 4;
            uint32_t a = (uint32_t)(r * 128 + (((c >> 3) ^ (r & 7)) << 4) + ((c & 7) << 1));
            uint32_t h0, l0, h1, l1;
            split2(v.x * 0.125f, v.y * 0.125f, h0, l0);
            split2(v.z * 0.125f, v.w * 0.125f, h1, l1);
            *(uint2*)(smp + a)         = make_uint2(h0, h1);
            *(uint2*)(smp + 16384 + a) = make_uint2(l0, l1);
        }
    }

    float o[8][4];
#pragma unroll
    for (int nt = 0; nt < 8; nt++)
#pragma unroll
        for (int k = 0; k < 4; k++) o[nt][k] = 0.f;
    float m0r = -INFINITY, m1r = -INFINITY, l0r = 0.f, l1r = 0.f;

    const int grow0 = q0 + wm + (lane >> 2);
    const int grow1 = grow0 + 8;
    const int nkt = 2 * qt + 2;

    for (int kt = 0; kt < nkt; kt++) {
        const int k0 = kt << 6;
        const int st = kt & 1;
        if (kt + 1 < nkt) {
            pf(kt + 1, st ^ 1); cp_commit();
            cp_wait<1>();
        } else {
            cp_wait<0>();
        }
        __syncthreads();

        const uint32_t sKHb = sKV + st * 32768;
        const uint32_t sKLb = sKHb + 8192;
        const uint32_t sVHb = sKHb + 16384;
        const uint32_t sVLb = sKHb + 24576;

        // ---- S = Q K^T (bf16x3, pass-reordered) ----
        float s[8][4];
#pragma unroll
        for (int nt = 0; nt < 8; nt++)
#pragma unroll
            for (int k = 0; k < 4; k++) s[nt][k] = 0.f;

#pragma unroll
        for (int ks = 0; ks < 4; ks++) {
            const int ck = ks * 2 + (lane >> 4);
            uint32_t qh[4], ql[4];
            ldsm4(qh, taddr(sQH, wm + lrow, ck));
            ldsm4(ql, taddr(sQL, wm + lrow, ck));
#pragma unroll
            for (int half = 0; half < 2; half++) {
                uint32_t r0h[4], r0l[4], r1h[4], r1l[4];
                ldsm4(r0h, taddr(sKHb, (half * 2) * 16 + lrow, ck));
                ldsm4(r0l, taddr(sKLb, (half * 2) * 16 + lrow, ck));
                ldsm4(r1h, taddr(sKHb, (half * 2 + 1) * 16 + lrow, ck));
                ldsm4(r1l, taddr(sKLb, (half * 2 + 1) * 16 + lrow, ck));
                const int n0 = half * 4;
                // pass Qh*Kh
                mma2(s[n0],     qh, r0h[0], r0h[2]);
                mma2(s[n0 + 1], qh, r0h[1], r0h[3]);
                mma2(s[n0 + 2], qh, r1h[0], r1h[2]);
                mma2(s[n0 + 3], qh, r1h[1], r1h[3]);
                // pass Ql*Kh
                mma2(s[n0],     ql, r0h[0], r0h[2]);
                mma2(s[n0 + 1], ql, r0h[1], r0h[3]);
                mma2(s[n0 + 2], ql, r1h[0], r1h[2]);
                mma2(s[n0 + 3], ql, r1h[1], r1h[3]);
                // pass Qh*Kl
                mma2(s[n0],     qh, r0l[0], r0l[2]);
                mma2(s[n0 + 1], qh, r0l[1], r0l[3]);
                mma2(s[n0 + 2], qh, r1l[0], r1l[2]);
                mma2(s[n0 + 3], qh, r1l[1], r1l[3]);
            }
        }

        // ---- causal mask ----
        if (k0 + 63 > grow0) {
#pragma unroll
            for (int nt = 0; nt < 8; nt++) {
                int col = k0 + nt * 8 + ((lane & 3) << 1);
                if (col > grow0)     s[nt][0] = -1e30f;
                if (col + 1 > grow0) s[nt][1] = -1e30f;
                if (col > grow1)     s[nt][2] = -1e30f;
                if (col + 1 > grow1) s[nt][3] = -1e30f;
            }
        }

        // ---- online softmax ----
        float ml0 = -INFINITY, ml1 = -INFINITY;
#pragma unroll
        for (int nt = 0; nt < 8; nt++) {
            ml0 = fmaxf(ml0, fmaxf(s[nt][0], s[nt][1]));
            ml1 = fmaxf(ml1, fmaxf(s[nt][2], s[nt][3]));
        }
        ml0 = fmaxf(ml0, __shfl_xor_sync(0xffffffffu, ml0, 1));
        ml0 = fmaxf(ml0, __shfl_xor_sync(0xffffffffu, ml0, 2));
        ml1 = fmaxf(ml1, __shfl_xor_sync(0xffffffffu, ml1, 1));
        ml1 = fmaxf(ml1, __shfl_xor_sync(0xffffffffu, ml1, 2));
        float mn0 = fmaxf(m0r, ml0), mn1 = fmaxf(m1r, ml1);
        float c0 = __expf(m0r - mn0), c1 = __expf(m1r - mn1);
        m0r = mn0; m1r = mn1;
        float rs0 = 0.f, rs1 = 0.f;
#pragma unroll
        for (int nt = 0; nt < 8; nt++) {
            s[nt][0] = __expf(s[nt][0] - mn0);
            s[nt][1] = __expf(s[nt][1] - mn0);
            s[nt][2] = __expf(s[nt][2] - mn1);
            s[nt][3] = __expf(s[nt][3] - mn1);
            rs0 += s[nt][0] + s[nt][1];
            rs1 += s[nt][2] + s[nt][3];
        }
        rs0 += __shfl_xor_sync(0xffffffffu, rs0, 1);
        rs0 += __shfl_xor_sync(0xffffffffu, rs0, 2);
        rs1 += __shfl_xor_sync(0xffffffffu, rs1, 1);
        rs1 += __shfl_xor_sync(0xffffffffu, rs1, 2);
        l0r = l0r * c0 + rs0;
        l1r = l1r * c1 + rs1;
#pragma unroll
        for (int nt = 0; nt < 8; nt++) {
            o[nt][0] *= c0; o[nt][1] *= c0;
            o[nt][2] *= c1; o[nt][3] *= c1;
        }

        // ---- O += P V  (pass-reordered) ----
#pragma unroll
        for (int j = 0; j < 4; j++) {
            uint32_t aPh[4], aPl[4];
            split2(s[2 * j][0],     s[2 * j][1],     aPh[0], aPl[0]);
            split2(s[2 * j][2],     s[2 * j][3],     aPh[1], aPl[1]);
            split2(s[2 * j + 1][0], s[2 * j + 1][1], aPh[2], aPl[2]);
            split2(s[2 * j + 1][2], s[2 * j + 1][3], aPh[3], aPl[3]);
#pragma unroll
            for (int half = 0; half < 2; half++) {
                const int ck0 = (half * 2) * 2 + (lane >> 4);
                const int ck1 = (half * 2 + 1) * 2 + (lane >> 4);
                uint32_t v0h[4], v0l[4], v1h[4], v1l[4];
                ldsm4t(v0h, taddr(sVHb, j * 16 + lrow, ck0));
                ldsm4t(v0l, taddr(sVLb, j * 16 + lrow, ck0));
                ldsm4t(v1h, taddr(sVHb, j * 16 + lrow, ck1));
                ldsm4t(v1l, taddr(sVLb, j * 16 + lrow, ck1));
                const int c0i = half * 4;
                // pass Ph*Vh
                mma2(o[c0i],     aPh, v0h[0], v0h[1]);
                mma2(o[c0i + 1], aPh, v0h[2], v0h[3]);
                mma2(o[c0i + 2], aPh, v1h[0], v1h[1]);
                mma2(o[c0i + 3], aPh, v1h[2], v1h[3]);
                // pass Pl*Vh
                mma2(o[c0i],     aPl, v0h[0], v0h[1]);
                mma2(o[c0i + 1], aPl, v0h[2], v0h[3]);
                mma2(o[c0i + 2], aPl, v1h[0], v1h[1]);
                mma2(o[c0i + 3], aPl, v1h[2], v1h[3]);
                // pass Ph*Vl
                mma2(o[c0i],     aPh, v0l[0], v0l[1]);
                mma2(o[c0i + 1], aPh, v0l[2], v0l[3]);
                mma2(o[c0i + 2], aPh, v1l[0], v1l[1]);
                mma2(o[c0i + 3], aPh, v1l[2], v1l[3]);
            }
        }
        __syncthreads();
    }

    // ---- epilogue ----
    float inv0 = 1.f / l0r, inv1 = 1.f / l1r;
    size_t r0 = (size_t)(b * SS + grow0) * DD;
    size_t r1 = (size_t)(b * SS + grow1) * DD;
    int colb = h * HDD + ((lane & 3) << 1);
#pragma unroll
    for (int nt = 0; nt < 8; nt++) {
        int col = colb + nt * 8;
        uint32_t hp, lp;
        split2(o[nt][0] * inv0, o[nt][1] * inv0, hp, lp);
        *(uint32_t*)(out_hi + r0 + col) = hp;
        *(uint32_t*)(out_lo + r0 + col) = lp;
        split2(o[nt][2] * inv1, o[nt][3] * inv1, hp, lp);
        *(uint32_t*)(out_hi + r1 + col) = hp;
        *(uint32_t*)(out_lo + r1 + col) = lp;
    }
}

// ---------------------------------------------------------------------------
extern "C" void kernel_launch(void* const* d_in, const int* in_sizes, int n_in,
                              void* d_out, int out_size)
{
    const float* x  = (const float*)d_in[0];
    const float* w1 = (const float*)d_in[1];
    const float* b1 = (const float*)d_in[2];
    const float* w2 = (const float*)d_in[3];
    const float* b2 = (const float*)d_in[4];
    float* out = (float*)d_out;

    float* qkv;
    __nv_bfloat16 *xhi, *xlo, *w1hi, *w1lo, *w2hi, *w2lo, *ahi, *alo;
    __nv_bfloat16 *khi, *klo, *vhi, *vlo;
    cudaGetSymbolAddress((void**)&qkv,  g_qkv);
    cudaGetSymbolAddress((void**)&xhi,  g_xhi);
    cudaGetSymbolAddress((void**)&xlo,  g_xlo);
    cudaGetSymbolAddress((void**)&w1hi, g_w1hi);
    cudaGetSymbolAddress((void**)&w1lo, g_w1lo);
    cudaGetSymbolAddress((void**)&w2hi, g_w2hi);
    cudaGetSymbolAddress((void**)&w2lo, g_w2lo);
    cudaGetSymbolAddress((void**)&ahi,  g_ahi);
    cudaGetSymbolAddress((void**)&alo,  g_alo);
    cudaGetSymbolAddress((void**)&khi,  g_khi);
    cudaGetSymbolAddress((void**)&klo,  g_klo);
    cudaGetSymbolAddress((void**)&vhi,  g_vhi);
    cudaGetSymbolAddress((void**)&vlo,  g_vlo);

    static int inited = 0;
    if (!inited) {
        cudaFuncSetAttribute(gemm_mma,
            cudaFuncAttributeMaxDynamicSharedMemorySize, GEMM_SMEM);
        cudaFuncSetAttribute(flash_attn_tc,
            cudaFuncAttributeMaxDynamicSharedMemorySize, FL_SMEM);
        inited = 1;
    }

    // 0) operand prep
    split_f32<<<(MM * KK / 4 + 255) / 256, 256>>>(x, xhi, xlo, MM * KK / 4);
    transpose_split<<<dim3(3 * DD / 32, KK / 32), dim3(32, 8)>>>(w1, w1hi, w1lo, KK, 3 * DD);
    transpose_split<<<dim3(DD / 32, KK / 32), dim3(32, 8)>>>(w2, w2hi, w2lo, KK, DD);

    // 1) QKV projection (tensor cores)
    gemm_mma<<<dim3(3 * DD / 128, MM / 128), 256, GEMM_SMEM>>>(
        xhi, xlo, w1hi, w1lo, b1, qkv, 3 * DD);

    // 1b) split K/V into bf16 hi/lo for flash cp.async path
    kv_split<<<(MM * DD / 4 + 255) / 256, 256>>>(qkv, khi, klo, vhi, vlo);

    // 2) causal flash attention on tensor cores
    flash_attn_tc<<<dim3(SS / 128, HH, BB), 256, FL_SMEM>>>(
        qkv, khi, klo, vhi, vlo, ahi, alo);

    // 3) output projection (tensor cores)
    gemm_mma<<<dim3(DD / 128, MM / 128), 256, GEMM_SMEM>>>(
        ahi, alo, w2hi, w2lo, b2, out, DD);
}

// round 6
// speedup vs baseline: 4.5446x; 1.3814x over previous
#include <cuda_runtime.h>
#include <cuda_fp16.h>
#include <math.h>
#include <stdint.h>

#define BB 2
#define SS 2048
#define DD 1024
#define HH 16
#define HDD 64
#define MM (BB*SS)          // 4096
#define KK DD               // 1024

// ---------------- device scratch (no runtime allocation allowed) ----------------
__device__ float g_qkv[(size_t)MM * 3 * DD];       // fp32 qkv
__device__ __half g_xhi[(size_t)MM * KK];          // x hi/lo (compensated A)
__device__ __half g_xlo[(size_t)MM * KK];
__device__ __half g_w1h[(size_t)3 * DD * KK];      // transposed [3D, K], fp16
__device__ __half g_w2h[(size_t)DD * KK];          // transposed [D, K], fp16
__device__ __half g_ahi[(size_t)MM * DD];          // attention out hi/lo
__device__ __half g_alo[(size_t)MM * DD];
__device__ __half g_kh[(size_t)MM * DD];           // K, V fp16 for flash
__device__ __half g_vh[(size_t)MM * DD];

// ---------------- PTX helpers (base sm_80+ ISA only) ----------
__device__ __forceinline__ uint32_t smem_u32(const void* p) {
    uint32_t a;
    asm("{ .reg .u64 t; cvta.to.shared.u64 t, %1; cvt.u32.u64 %0, t; }" : "=r"(a) : "l"(p));
    return a;
}
__device__ __forceinline__ void cp16(uint32_t dst, const void* src) {
    asm volatile("cp.async.cg.shared.global [%0], [%1], 16;" :: "r"(dst), "l"(src));
}
__device__ __forceinline__ void cp_commit() {
    asm volatile("cp.async.commit_group;" ::: "memory");
}
template <int N>
__device__ __forceinline__ void cp_wait() {
    asm volatile("cp.async.wait_group %0;" :: "n"(N) : "memory");
}
__device__ __forceinline__ void ldsm4(uint32_t* r, uint32_t addr) {
    asm volatile("ldmatrix.sync.aligned.m8n8.x4.shared.b16 {%0,%1,%2,%3}, [%4];"
                 : "=r"(r[0]), "=r"(r[1]), "=r"(r[2]), "=r"(r[3]) : "r"(addr));
}
__device__ __forceinline__ void ldsm4t(uint32_t* r, uint32_t addr) {
    asm volatile("ldmatrix.sync.aligned.m8n8.x4.trans.shared.b16 {%0,%1,%2,%3}, [%4];"
                 : "=r"(r[0]), "=r"(r[1]), "=r"(r[2]), "=r"(r[3]) : "r"(addr));
}
// fp16 MMA
__device__ __forceinline__ void mma2(float* d, const uint32_t* a, uint32_t b0, uint32_t b1) {
    asm volatile(
        "mma.sync.aligned.m16n8k16.row.col.f32.f16.f16.f32 "
        "{%0,%1,%2,%3}, {%4,%5,%6,%7}, {%8,%9}, {%0,%1,%2,%3};"
        : "+f"(d[0]), "+f"(d[1]), "+f"(d[2]), "+f"(d[3])
        : "r"(a[0]), "r"(a[1]), "r"(a[2]), "r"(a[3]), "r"(b0), "r"(b1));
}
__device__ __forceinline__ uint32_t pkh(float a, float b) {
    __half2 h = __floats2half2_rn(a, b);
    return *(uint32_t*)&h;
}
// fp16 hi/lo split of a pair -> packed half2 hi and lo
__device__ __forceinline__ void split2h(float a, float b, uint32_t& hi, uint32_t& lo) {
    __half2 h = __floats2half2_rn(a, b);
    hi = *(uint32_t*)&h;
    float2 f = __half22float2(h);
    __half2 l = __floats2half2_rn(a - f.x, b - f.y);
    lo = *(uint32_t*)&l;
}

// ========================== GEMM ==========================
__device__ __forceinline__ uint32_t swz(int row, int c) {
    return (uint32_t)(row * 64 + ((c ^ ((row >> 1) & 3)) << 4));
}
#define TILE_BYTES 8192                 // 128 rows x 32 fp16
#define STAGE_BYTES (3 * TILE_BYTES)    // Ah, Al, Bh
#define GEMM_SMEM  (3 * STAGE_BYTES)    // 72 KB, 3 stages

// C[M,N] = (Ah+Al)[M,K] @ Bh[N,K]^T + bias   (fp16x2, error ~2^-11 rel)
__global__ void __launch_bounds__(256, 2) gemm_mma(
    const __half* __restrict__ Ahi, const __half* __restrict__ Alo,
    const __half* __restrict__ Bh,
    const float* __restrict__ bias, float* __restrict__ C, int N)
{
    extern __shared__ char smem[];
    const uint32_t sbase = smem_u32(smem);
    const int tid  = threadIdx.x;
    const int wid  = tid >> 5;
    const int lane = tid & 31;
    const int wm = (wid >> 2) * 64;
    const int wn = (wid & 3) * 32;
    const int m0 = blockIdx.y << 7;
    const int n0 = blockIdx.x << 7;

    const __half* srcs[3] = {
        Ahi + (size_t)m0 * KK, Alo + (size_t)m0 * KK, Bh + (size_t)n0 * KK };

    auto prefetch = [&](int kt, int s) {
        uint32_t stb = sbase + s * STAGE_BYTES;
#pragma unroll
        for (int t = 0; t < 3; t++) {
            const __half* g = srcs[t] + kt * 32;
#pragma unroll
            for (int i = 0; i < 2; i++) {
                int cid = i * 256 + tid;
                int row = cid >> 2, c = cid & 3;
                cp16(stb + t * TILE_BYTES + swz(row, c),
                     g + (size_t)row * KK + c * 8);
            }
        }
    };

    float acc[4][4][4];
#pragma unroll
    for (int i = 0; i < 4; i++)
#pragma unroll
        for (int j = 0; j < 4; j++)
#pragma unroll
            for (int k = 0; k < 4; k++) acc[i][j][k] = 0.f;

    prefetch(0, 0); cp_commit();
    prefetch(1, 1); cp_commit();

    const int KCH = KK / 32;   // 32
    for (int kt = 0; kt < KCH; kt++) {
        const int s = kt % 3;
        if (kt == KCH - 1) cp_wait<0>(); else cp_wait<1>();
        __syncthreads();

        const uint32_t ahb = sbase + s * STAGE_BYTES;
        const uint32_t alb = ahb + TILE_BYTES;
        const uint32_t bhb = ahb + 2 * TILE_BYTES;

#pragma unroll
        for (int kh = 0; kh < 2; kh++) {
            const int lrow = lane & 15;
            const int lkc  = kh * 2 + (lane >> 4);

            uint32_t ah[4][4], al[4][4];
#pragma unroll
            for (int mt = 0; mt < 4; mt++) {
                uint32_t off = swz(wm + mt * 16 + lrow, lkc);
                ldsm4(ah[mt], ahb + off);
                ldsm4(al[mt], alb + off);
            }
#pragma unroll
            for (int nh = 0; nh < 2; nh++) {
                uint32_t off = swz(wn + nh * 16 + lrow, lkc);
                uint32_t rb[4];
                ldsm4(rb, bhb + off);
                const int nb = nh * 2;
#pragma unroll
                for (int mt = 0; mt < 4; mt++) {
                    mma2(acc[mt][nb],     ah[mt], rb[0], rb[2]);
                    mma2(acc[mt][nb + 1], ah[mt], rb[1], rb[3]);
                }
#pragma unroll
                for (int mt = 0; mt < 4; mt++) {
                    mma2(acc[mt][nb],     al[mt], rb[0], rb[2]);
                    mma2(acc[mt][nb + 1], al[mt], rb[1], rb[3]);
                }
            }
        }
        __syncthreads();
        if (kt + 2 < KCH) { prefetch(kt + 2, (kt + 2) % 3); cp_commit(); }
    }

#pragma unroll
    for (int mt = 0; mt < 4; mt++) {
#pragma unroll
        for (int nt = 0; nt < 4; nt++) {
            int row = m0 + wm + mt * 16 + (lane >> 2);
            int col = n0 + wn + nt * 8 + ((lane & 3) << 1);
            float b0 = __ldg(bias + col), b1 = __ldg(bias + col + 1);
            float* d = acc[mt][nt];
            *(float2*)(C + (size_t)row * N + col) =
                make_float2(d[0] + b0, d[1] + b1);
            *(float2*)(C + (size_t)(row + 8) * N + col) =
                make_float2(d[2] + b0, d[3] + b1);
        }
    }
}

// ========================== prep kernels ==========================
__global__ void split_x(const float* __restrict__ in,
                        __half* __restrict__ hi, __half* __restrict__ lo, int n4)
{
    int i = blockIdx.x * blockDim.x + threadIdx.x;
    if (i >= n4) return;
    float4 v = ((const float4*)in)[i];
    uint32_t h0, l0, h1, l1;
    split2h(v.x, v.y, h0, l0);
    split2h(v.z, v.w, h1, l1);
    ((uint2*)hi)[i] = make_uint2(h0, h1);
    ((uint2*)lo)[i] = make_uint2(l0, l1);
}

// W[K,N] fp32 -> transposed fp16 [N,K]
__global__ void transpose_h(const float* __restrict__ in,
                            __half* __restrict__ hi, int K, int N)
{
    __shared__ float t[32][33];
    int bx = blockIdx.x << 5;
    int by = blockIdx.y << 5;
    int tx = threadIdx.x, ty = threadIdx.y;
#pragma unroll
    for (int i = 0; i < 32; i += 8)
        t[ty + i][tx] = in[(size_t)(by + ty + i) * N + bx + tx];
    __syncthreads();
#pragma unroll
    for (int i = 0; i < 32; i += 8) {
        int n = bx + ty + i, k = by + tx;
        hi[(size_t)n * K + k] = __float2half_rn(t[tx][ty + i]);
    }
}

// qkv K,V sections -> fp16 [B*S, D]
__global__ void kv_half(const float* __restrict__ qkv,
                        __half* __restrict__ kh, __half* __restrict__ vh)
{
    int i = blockIdx.x * blockDim.x + threadIdx.x;
    if (i >= MM * DD / 4) return;
    int row = i >> 8;
    int c4  = (i & 255) << 2;
    const float* base = qkv + (size_t)row * 3 * DD + c4;
    float4 kv = *(const float4*)(base + DD);
    float4 vv = *(const float4*)(base + 2 * DD);
    ((uint2*)kh)[i] = make_uint2(pkh(kv.x, kv.y), pkh(kv.z, kv.w));
    ((uint2*)vh)[i] = make_uint2(pkh(vv.x, vv.y), pkh(vv.z, vv.w));
}

// ========================== tensor-core flash attention ==========================
__device__ __forceinline__ uint32_t taddr(uint32_t base, int row, int chunk) {
    return base + (uint32_t)(row * 128) + (uint32_t)((chunk ^ (row & 7)) << 4);
}

#define FL_SMEM 65536
// layout: QH 0 (16K), QL 16K, then 2 stages of 16K: {KH 8K, VH 8K}

__global__ void __launch_bounds__(256, 2) flash_attn_tc(
    const float* __restrict__ qkv,
    const __half* __restrict__ khg, const __half* __restrict__ vhg,
    __half* __restrict__ out_hi, __half* __restrict__ out_lo)
{
    extern __shared__ char sm[];
    const uint32_t sQH = smem_u32(sm);
    const uint32_t sQL = sQH + 16384;
    const uint32_t sKV = sQH + 32768;
    char* smp = sm;

    const int tid  = threadIdx.x;
    const int wid  = tid >> 5;
    const int lane = tid & 31;
    const int lrow = lane & 15;
    const int wm   = wid << 4;
    const int qt   = (gridDim.x - 1) - blockIdx.x;   // heavy tiles first
    const int h    = blockIdx.y;
    const int b    = blockIdx.z;
    const int q0   = qt << 7;
    const size_t rstride = 3 * DD;

    // K/V prefetch (cp.async, fp16, swizzled 128B rows)
    auto pf = [&](int kt, int st) {
        uint32_t sb = sKV + st * 16384;
        const size_t goff = (size_t)(b * SS + (kt << 6)) * DD + h * HDD;
#pragma unroll
        for (int t = 0; t < 4; t++) {
            const __half* gp = (t < 2) ? khg : vhg;
            int cid = ((t & 1) << 8) + tid;     // 0..511
            int row = cid >> 3, c = cid & 7;
            cp16(sb + (uint32_t)(((t >> 1) << 13) + row * 128 + ((c ^ (row & 7)) << 4)),
                 gp + goff + (size_t)row * DD + c * 8);
        }
    };

    pf(0, 0); cp_commit();

    // load Q (scaled by 1/8), split fp16 hi/lo into smem
    {
        int r  = tid >> 1;
        int cb = (tid & 1) << 5;
        const float* qp = qkv + (size_t)(b * SS + q0 + r) * rstride + h * HDD + cb;
#pragma unroll
        for (int i = 0; i < 8; i++) {
            float4 v = *(const float4*)(qp + i * 4);
            int c = cb + i * 4;
            uint32_t a = (uint32_t)(r * 128 + (((c >> 3) ^ (r & 7)) << 4) + ((c & 7) << 1));
            uint32_t h0, l0, h1, l1;
            split2h(v.x * 0.125f, v.y * 0.125f, h0, l0);
            split2h(v.z * 0.125f, v.w * 0.125f, h1, l1);
            *(uint2*)(smp + a)         = make_uint2(h0, h1);
            *(uint2*)(smp + 16384 + a) = make_uint2(l0, l1);
        }
    }

    float o[8][4];
#pragma unroll
    for (int nt = 0; nt < 8; nt++)
#pragma unroll
        for (int k = 0; k < 4; k++) o[nt][k] = 0.f;
    float m0r = -INFINITY, m1r = -INFINITY, l0r = 0.f, l1r = 0.f;

    const int grow0 = q0 + wm + (lane >> 2);
    const int grow1 = grow0 + 8;
    const int nkt = 2 * qt + 2;

    for (int kt = 0; kt < nkt; kt++) {
        const int k0 = kt << 6;
        const int st = kt & 1;
        if (kt + 1 < nkt) {
            pf(kt + 1, st ^ 1); cp_commit();
            cp_wait<1>();
        } else {
            cp_wait<0>();
        }
        __syncthreads();

        const uint32_t sKHb = sKV + st * 16384;
        const uint32_t sVHb = sKHb + 8192;

        // ---- S = (Qh+Ql) K^T ----
        float s[8][4];
#pragma unroll
        for (int nt = 0; nt < 8; nt++)
#pragma unroll
            for (int k = 0; k < 4; k++) s[nt][k] = 0.f;

#pragma unroll
        for (int ks = 0; ks < 4; ks++) {
            const int ck = ks * 2 + (lane >> 4);
            uint32_t qh[4], ql[4];
            ldsm4(qh, taddr(sQH, wm + lrow, ck));
            ldsm4(ql, taddr(sQL, wm + lrow, ck));
#pragma unroll
            for (int half = 0; half < 2; half++) {
                uint32_t r0[4], r1[4];
                ldsm4(r0, taddr(sKHb, half * 32 + lrow, ck));
                ldsm4(r1, taddr(sKHb, half * 32 + 16 + lrow, ck));
                const int n0 = half * 4;
                mma2(s[n0],     qh, r0[0], r0[2]);
                mma2(s[n0 + 1], qh, r0[1], r0[3]);
                mma2(s[n0 + 2], qh, r1[0], r1[2]);
                mma2(s[n0 + 3], qh, r1[1], r1[3]);
                mma2(s[n0],     ql, r0[0], r0[2]);
                mma2(s[n0 + 1], ql, r0[1], r0[3]);
                mma2(s[n0 + 2], ql, r1[0], r1[2]);
                mma2(s[n0 + 3], ql, r1[1], r1[3]);
            }
        }

        // ---- causal mask ----
        if (k0 + 63 > grow0) {
#pragma unroll
            for (int nt = 0; nt < 8; nt++) {
                int col = k0 + nt * 8 + ((lane & 3) << 1);
                if (col > grow0)     s[nt][0] = -1e30f;
                if (col + 1 > grow0) s[nt][1] = -1e30f;
                if (col > grow1)     s[nt][2] = -1e30f;
                if (col + 1 > grow1) s[nt][3] = -1e30f;
            }
        }

        // ---- online softmax ----
        float ml0 = -INFINITY, ml1 = -INFINITY;
#pragma unroll
        for (int nt = 0; nt < 8; nt++) {
            ml0 = fmaxf(ml0, fmaxf(s[nt][0], s[nt][1]));
            ml1 = fmaxf(ml1, fmaxf(s[nt][2], s[nt][3]));
        }
        ml0 = fmaxf(ml0, __shfl_xor_sync(0xffffffffu, ml0, 1));
        ml0 = fmaxf(ml0, __shfl_xor_sync(0xffffffffu, ml0, 2));
        ml1 = fmaxf(ml1, __shfl_xor_sync(0xffffffffu, ml1, 1));
        ml1 = fmaxf(ml1, __shfl_xor_sync(0xffffffffu, ml1, 2));
        float mn0 = fmaxf(m0r, ml0), mn1 = fmaxf(m1r, ml1);
        float c0 = __expf(m0r - mn0), c1 = __expf(m1r - mn1);
        m0r = mn0; m1r = mn1;
        float rs0 = 0.f, rs1 = 0.f;
#pragma unroll
        for (int nt = 0; nt < 8; nt++) {
            s[nt][0] = __expf(s[nt][0] - mn0);
            s[nt][1] = __expf(s[nt][1] - mn0);
            s[nt][2] = __expf(s[nt][2] - mn1);
            s[nt][3] = __expf(s[nt][3] - mn1);
            rs0 += s[nt][0] + s[nt][1];
            rs1 += s[nt][2] + s[nt][3];
        }
        rs0 += __shfl_xor_sync(0xffffffffu, rs0, 1);
        rs0 += __shfl_xor_sync(0xffffffffu, rs0, 2);
        rs1 += __shfl_xor_sync(0xffffffffu, rs1, 1);
        rs1 += __shfl_xor_sync(0xffffffffu, rs1, 2);
        l0r = l0r * c0 + rs0;
        l1r = l1r * c1 + rs1;
#pragma unroll
        for (int nt = 0; nt < 8; nt++) {
            o[nt][0] *= c0; o[nt][1] *= c0;
            o[nt][2] *= c1; o[nt][3] *= c1;
        }

        // ---- O += (Ph+Pl) V ----
#pragma unroll
        for (int j = 0; j < 4; j++) {
            uint32_t aPh[4], aPl[4];
            split2h(s[2 * j][0],     s[2 * j][1],     aPh[0], aPl[0]);
            split2h(s[2 * j][2],     s[2 * j][3],     aPh[1], aPl[1]);
            split2h(s[2 * j + 1][0], s[2 * j + 1][1], aPh[2], aPl[2]);
            split2h(s[2 * j + 1][2], s[2 * j + 1][3], aPh[3], aPl[3]);
#pragma unroll
            for (int half = 0; half < 2; half++) {
                const int ck0 = half * 4 + (lane >> 4);
                const int ck1 = ck0 + 2;
                uint32_t v0[4], v1[4];
                ldsm4t(v0, taddr(sVHb, j * 16 + lrow, ck0));
                ldsm4t(v1, taddr(sVHb, j * 16 + lrow, ck1));
                const int c0i = half * 4;
                mma2(o[c0i],     aPh, v0[0], v0[1]);
                mma2(o[c0i + 1], aPh, v0[2], v0[3]);
                mma2(o[c0i + 2], aPh, v1[0], v1[1]);
                mma2(o[c0i + 3], aPh, v1[2], v1[3]);
                mma2(o[c0i],     aPl, v0[0], v0[1]);
                mma2(o[c0i + 1], aPl, v0[2], v0[3]);
                mma2(o[c0i + 2], aPl, v1[0], v1[1]);
                mma2(o[c0i + 3], aPl, v1[2], v1[3]);
            }
        }
        __syncthreads();
    }

    // ---- epilogue: normalize, split fp16 hi/lo, store merged-head [B*S, D] ----
    float inv0 = 1.f / l0r, inv1 = 1.f / l1r;
    size_t r0 = (size_t)(b * SS + grow0) * DD;
    size_t r1 = (size_t)(b * SS + grow1) * DD;
    int colb = h * HDD + ((lane & 3) << 1);
#pragma unroll
    for (int nt = 0; nt < 8; nt++) {
        int col = colb + nt * 8;
        uint32_t hp, lp;
        split2h(o[nt][0] * inv0, o[nt][1] * inv0, hp, lp);
        *(uint32_t*)(out_hi + r0 + col) = hp;
        *(uint32_t*)(out_lo + r0 + col) = lp;
        split2h(o[nt][2] * inv1, o[nt][3] * inv1, hp, lp);
        *(uint32_t*)(out_hi + r1 + col) = hp;
        *(uint32_t*)(out_lo + r1 + col) = lp;
    }
}

// ---------------------------------------------------------------------------
extern "C" void kernel_launch(void* const* d_in, const int* in_sizes, int n_in,
                              void* d_out, int out_size)
{
    const float* x  = (const float*)d_in[0];
    const float* w1 = (const float*)d_in[1];
    const float* b1 = (const float*)d_in[2];
    const float* w2 = (const float*)d_in[3];
    const float* b2 = (const float*)d_in[4];
    float* out = (float*)d_out;

    float* qkv;
    __half *xhi, *xlo, *w1h, *w2h, *ahi, *alo, *kh, *vh;
    cudaGetSymbolAddress((void**)&qkv, g_qkv);
    cudaGetSymbolAddress((void**)&xhi, g_xhi);
    cudaGetSymbolAddress((void**)&xlo, g_xlo);
    cudaGetSymbolAddress((void**)&w1h, g_w1h);
    cudaGetSymbolAddress((void**)&w2h, g_w2h);
    cudaGetSymbolAddress((void**)&ahi, g_ahi);
    cudaGetSymbolAddress((void**)&alo, g_alo);
    cudaGetSymbolAddress((void**)&kh,  g_kh);
    cudaGetSymbolAddress((void**)&vh,  g_vh);

    static int inited = 0;
    if (!inited) {
        cudaFuncSetAttribute(gemm_mma,
            cudaFuncAttributeMaxDynamicSharedMemorySize, GEMM_SMEM);
        cudaFuncSetAttribute(flash_attn_tc,
            cudaFuncAttributeMaxDynamicSharedMemorySize, FL_SMEM);
        inited = 1;
    }

    // 0) operand prep
    split_x<<<(MM * KK / 4 + 255) / 256, 256>>>(x, xhi, xlo, MM * KK / 4);
    transpose_h<<<dim3(3 * DD / 32, KK / 32), dim3(32, 8)>>>(w1, w1h, KK, 3 * DD);
    transpose_h<<<dim3(DD / 32, KK / 32), dim3(32, 8)>>>(w2, w2h, KK, DD);

    // 1) QKV projection
    gemm_mma<<<dim3(3 * DD / 128, MM / 128), 256, GEMM_SMEM>>>(
        xhi, xlo, w1h, b1, qkv, 3 * DD);

    // 1b) K/V fp16 conversion for flash cp.async path
    kv_half<<<(MM * DD / 4 + 255) / 256, 256>>>(qkv, kh, vh);

    // 2) causal flash attention on tensor cores
    flash_attn_tc<<<dim3(SS / 128, HH, BB), 256, FL_SMEM>>>(
        qkv, kh, vh, ahi, alo);

    // 3) output projection
    gemm_mma<<<dim3(DD / 128, MM / 128), 256, GEMM_SMEM>>>(
        ahi, alo, w2h, b2, out, DD);
}

// round 7
// speedup vs baseline: 4.7335x; 1.0416x over previous
#include <cuda_runtime.h>
#include <cuda_fp16.h>
#include <math.h>
#include <stdint.h>

#define BB 2
#define SS 2048
#define DD 1024
#define HH 16
#define HDD 64
#define MM (BB*SS)          // 4096
#define KK DD               // 1024

// ---------------- device scratch (no runtime allocation allowed) ----------------
__device__ __half g_xhi[(size_t)MM * KK];          // x hi/lo (compensated A)
__device__ __half g_xlo[(size_t)MM * KK];
__device__ __half g_w1h[(size_t)3 * DD * KK];      // transposed [3D, K], fp16
__device__ __half g_w2h[(size_t)DD * KK];          // transposed [D, K], fp16
__device__ __half g_qhi[(size_t)MM * DD];          // Q pre-scaled hi/lo fp16
__device__ __half g_qlo[(size_t)MM * DD];
__device__ __half g_kh[(size_t)MM * DD];           // K fp16
__device__ __half g_vh[(size_t)MM * DD];           // V fp16
__device__ __half g_ahi[(size_t)MM * DD];          // attention out hi/lo
__device__ __half g_alo[(size_t)MM * DD];

// ---------------- PTX helpers (base sm_80+ ISA only) ----------
__device__ __forceinline__ uint32_t smem_u32(const void* p) {
    uint32_t a;
    asm("{ .reg .u64 t; cvta.to.shared.u64 t, %1; cvt.u32.u64 %0, t; }" : "=r"(a) : "l"(p));
    return a;
}
__device__ __forceinline__ void cp16(uint32_t dst, const void* src) {
    asm volatile("cp.async.cg.shared.global [%0], [%1], 16;" :: "r"(dst), "l"(src));
}
__device__ __forceinline__ void cp_commit() {
    asm volatile("cp.async.commit_group;" ::: "memory");
}
template <int N>
__device__ __forceinline__ void cp_wait() {
    asm volatile("cp.async.wait_group %0;" :: "n"(N) : "memory");
}
__device__ __forceinline__ void ldsm4(uint32_t* r, uint32_t addr) {
    asm volatile("ldmatrix.sync.aligned.m8n8.x4.shared.b16 {%0,%1,%2,%3}, [%4];"
                 : "=r"(r[0]), "=r"(r[1]), "=r"(r[2]), "=r"(r[3]) : "r"(addr));
}
__device__ __forceinline__ void ldsm4t(uint32_t* r, uint32_t addr) {
    asm volatile("ldmatrix.sync.aligned.m8n8.x4.trans.shared.b16 {%0,%1,%2,%3}, [%4];"
                 : "=r"(r[0]), "=r"(r[1]), "=r"(r[2]), "=r"(r[3]) : "r"(addr));
}
__device__ __forceinline__ void mma2(float* d, const uint32_t* a, uint32_t b0, uint32_t b1) {
    asm volatile(
        "mma.sync.aligned.m16n8k16.row.col.f32.f16.f16.f32 "
        "{%0,%1,%2,%3}, {%4,%5,%6,%7}, {%8,%9}, {%0,%1,%2,%3};"
        : "+f"(d[0]), "+f"(d[1]), "+f"(d[2]), "+f"(d[3])
        : "r"(a[0]), "r"(a[1]), "r"(a[2]), "r"(a[3]), "r"(b0), "r"(b1));
}
__device__ __forceinline__ uint32_t pkh(float a, float b) {
    __half2 h = __floats2half2_rn(a, b);
    return *(uint32_t*)&h;
}
__device__ __forceinline__ void split2h(float a, float b, uint32_t& hi, uint32_t& lo) {
    __half2 h = __floats2half2_rn(a, b);
    hi = *(uint32_t*)&h;
    float2 f = __half22float2(h);
    __half2 l = __floats2half2_rn(a - f.x, b - f.y);
    lo = *(uint32_t*)&l;
}

// ========================== GEMM ==========================
__device__ __forceinline__ uint32_t swz(int row, int c) {
    return (uint32_t)(row * 64 + ((c ^ ((row >> 1) & 3)) << 4));
}
#define TILE_BYTES 8192                 // 128 rows x 32 fp16
#define STAGE_BYTES (3 * TILE_BYTES)    // Ah, Al, Bh
#define GEMM_SMEM  (3 * STAGE_BYTES)    // 72 KB, 3 stages

// C = (Ah+Al)[M,K] @ Bh[N,K]^T + bias
// MODE 0: fp32 C output.  MODE 1: QKV fused epilogue — writes Q (scaled 1/8)
// as fp16 hi/lo, K and V as fp16, based on which third of N this CTA covers.
template <int MODE>
__global__ void __launch_bounds__(256, 2) gemm_mma(
    const __half* __restrict__ Ahi, const __half* __restrict__ Alo,
    const __half* __restrict__ Bh,
    const float* __restrict__ bias, float* __restrict__ C, int N,
    __half* __restrict__ qhi, __half* __restrict__ qlo,
    __half* __restrict__ khd, __half* __restrict__ vhd)
{
    extern __shared__ char smem[];
    const uint32_t sbase = smem_u32(smem);
    const int tid  = threadIdx.x;
    const int wid  = tid >> 5;
    const int lane = tid & 31;
    const int wm = (wid >> 2) * 64;
    const int wn = (wid & 3) * 32;
    const int m0 = blockIdx.y << 7;
    const int n0 = blockIdx.x << 7;

    const __half* srcs[3] = {
        Ahi + (size_t)m0 * KK, Alo + (size_t)m0 * KK, Bh + (size_t)n0 * KK };

    auto prefetch = [&](int kt, int s) {
        uint32_t stb = sbase + s * STAGE_BYTES;
#pragma unroll
        for (int t = 0; t < 3; t++) {
            const __half* g = srcs[t] + kt * 32;
#pragma unroll
            for (int i = 0; i < 2; i++) {
                int cid = i * 256 + tid;
                int row = cid >> 2, c = cid & 3;
                cp16(stb + t * TILE_BYTES + swz(row, c),
                     g + (size_t)row * KK + c * 8);
            }
        }
    };

    float acc[4][4][4];
#pragma unroll
    for (int i = 0; i < 4; i++)
#pragma unroll
        for (int j = 0; j < 4; j++)
#pragma unroll
            for (int k = 0; k < 4; k++) acc[i][j][k] = 0.f;

    prefetch(0, 0); cp_commit();
    prefetch(1, 1); cp_commit();

    const int KCH = KK / 32;   // 32
    for (int kt = 0; kt < KCH; kt++) {
        const int s = kt % 3;
        if (kt == KCH - 1) cp_wait<0>(); else cp_wait<1>();
        __syncthreads();

        const uint32_t ahb = sbase + s * STAGE_BYTES;
        const uint32_t alb = ahb + TILE_BYTES;
        const uint32_t bhb = ahb + 2 * TILE_BYTES;

#pragma unroll
        for (int kh = 0; kh < 2; kh++) {
            const int lrow = lane & 15;
            const int lkc  = kh * 2 + (lane >> 4);

            uint32_t ah[4][4], al[4][4];
#pragma unroll
            for (int mt = 0; mt < 4; mt++) {
                uint32_t off = swz(wm + mt * 16 + lrow, lkc);
                ldsm4(ah[mt], ahb + off);
                ldsm4(al[mt], alb + off);
            }
#pragma unroll
            for (int nh = 0; nh < 2; nh++) {
                uint32_t off = swz(wn + nh * 16 + lrow, lkc);
                uint32_t rb[4];
                ldsm4(rb, bhb + off);
                const int nb = nh * 2;
#pragma unroll
                for (int mt = 0; mt < 4; mt++) {
                    mma2(acc[mt][nb],     ah[mt], rb[0], rb[2]);
                    mma2(acc[mt][nb + 1], ah[mt], rb[1], rb[3]);
                }
#pragma unroll
                for (int mt = 0; mt < 4; mt++) {
                    mma2(acc[mt][nb],     al[mt], rb[0], rb[2]);
                    mma2(acc[mt][nb + 1], al[mt], rb[1], rb[3]);
                }
            }
        }
        __syncthreads();
        if (kt + 2 < KCH) { prefetch(kt + 2, (kt + 2) % 3); cp_commit(); }
    }

    if (MODE == 0) {
#pragma unroll
        for (int mt = 0; mt < 4; mt++) {
#pragma unroll
            for (int nt = 0; nt < 4; nt++) {
                int row = m0 + wm + mt * 16 + (lane >> 2);
                int col = n0 + wn + nt * 8 + ((lane & 3) << 1);
                float b0 = __ldg(bias + col), b1 = __ldg(bias + col + 1);
                float* d = acc[mt][nt];
                *(float2*)(C + (size_t)row * N + col) =
                    make_float2(d[0] + b0, d[1] + b1);
                *(float2*)(C + (size_t)(row + 8) * N + col) =
                    make_float2(d[2] + b0, d[3] + b1);
            }
        }
    } else {
        const int region = n0 >> 10;       // 0=Q, 1=K, 2=V
        const int ncol0  = n0 & 1023;
#pragma unroll
        for (int mt = 0; mt < 4; mt++) {
#pragma unroll
            for (int nt = 0; nt < 4; nt++) {
                int row  = m0 + wm + mt * 16 + (lane >> 2);
                int gcol = n0 + wn + nt * 8 + ((lane & 3) << 1);
                int col  = ncol0 + wn + nt * 8 + ((lane & 3) << 1);
                float b0 = __ldg(bias + gcol), b1 = __ldg(bias + gcol + 1);
                float* d = acc[mt][nt];
                float e0 = d[0] + b0, e1 = d[1] + b1;
                float e2 = d[2] + b0, e3 = d[3] + b1;
                if (region == 0) {
                    uint32_t hp, lp;
                    split2h(e0 * 0.125f, e1 * 0.125f, hp, lp);
                    *(uint32_t*)(qhi + (size_t)row * DD + col) = hp;
                    *(uint32_t*)(qlo + (size_t)row * DD + col) = lp;
                    split2h(e2 * 0.125f, e3 * 0.125f, hp, lp);
                    *(uint32_t*)(qhi + (size_t)(row + 8) * DD + col) = hp;
                    *(uint32_t*)(qlo + (size_t)(row + 8) * DD + col) = lp;
                } else {
                    __half* dst = (region == 1) ? khd : vhd;
                    *(uint32_t*)(dst + (size_t)row * DD + col)       = pkh(e0, e1);
                    *(uint32_t*)(dst + (size_t)(row + 8) * DD + col) = pkh(e2, e3);
                }
            }
        }
    }
}

// ========================== prep kernels ==========================
__global__ void split_x(const float* __restrict__ in,
                        __half* __restrict__ hi, __half* __restrict__ lo, int n4)
{
    int i = blockIdx.x * blockDim.x + threadIdx.x;
    if (i >= n4) return;
    float4 v = ((const float4*)in)[i];
    uint32_t h0, l0, h1, l1;
    split2h(v.x, v.y, h0, l0);
    split2h(v.z, v.w, h1, l1);
    ((uint2*)hi)[i] = make_uint2(h0, h1);
    ((uint2*)lo)[i] = make_uint2(l0, l1);
}

// W[K,N] fp32 -> transposed fp16 [N,K]
__global__ void transpose_h(const float* __restrict__ in,
                            __half* __restrict__ hi, int K, int N)
{
    __shared__ float t[32][33];
    int bx = blockIdx.x << 5;
    int by = blockIdx.y << 5;
    int tx = threadIdx.x, ty = threadIdx.y;
#pragma unroll
    for (int i = 0; i < 32; i += 8)
        t[ty + i][tx] = in[(size_t)(by + ty + i) * N + bx + tx];
    __syncthreads();
#pragma unroll
    for (int i = 0; i < 32; i += 8) {
        int n = bx + ty + i, k = by + tx;
        hi[(size_t)n * K + k] = __float2half_rn(t[tx][ty + i]);
    }
}

// ========================== tensor-core flash attention ==========================
__device__ __forceinline__ uint32_t taddr(uint32_t base, int row, int chunk) {
    return base + (uint32_t)(row * 128) + (uint32_t)((chunk ^ (row & 7)) << 4);
}

#define FL_SMEM 65536
// layout: QH 0 (16K), QL 16K, then 2 stages of 16K: {KH 8K, VH 8K}

__global__ void __launch_bounds__(256, 2) flash_attn_tc(
    const __half* __restrict__ qhig, const __half* __restrict__ qlog,
    const __half* __restrict__ khg,  const __half* __restrict__ vhg,
    __half* __restrict__ out_hi, __half* __restrict__ out_lo)
{
    extern __shared__ char sm[];
    const uint32_t sQH = smem_u32(sm);
    const uint32_t sQL = sQH + 16384;
    const uint32_t sKV = sQH + 32768;

    const int tid  = threadIdx.x;
    const int wid  = tid >> 5;
    const int lane = tid & 31;
    const int lrow = lane & 15;
    const int wm   = wid << 4;
    const int qt   = (gridDim.x - 1) - blockIdx.x;   // heavy tiles first
    const int h    = blockIdx.y;
    const int b    = blockIdx.z;
    const int q0   = qt << 7;

    // ---- Q prefetch (cp.async, pre-scaled pre-split fp16) ----
    {
        const __half* qsrc[2] = {
            qhig + (size_t)(b * SS + q0) * DD + h * HDD,
            qlog + (size_t)(b * SS + q0) * DD + h * HDD };
#pragma unroll
        for (int t = 0; t < 2; t++) {
#pragma unroll
            for (int i = 0; i < 4; i++) {
                int cid = i * 256 + tid;          // 0..1023
                int row = cid >> 3, c = cid & 7;
                cp16(sQH + (uint32_t)(t * 16384 + row * 128 + ((c ^ (row & 7)) << 4)),
                     qsrc[t] + (size_t)row * DD + c * 8);
            }
        }
        cp_commit();
    }

    // ---- K/V prefetch ----
    auto pf = [&](int kt, int st) {
        uint32_t sb = sKV + st * 16384;
        const size_t goff = (size_t)(b * SS + (kt << 6)) * DD + h * HDD;
#pragma unroll
        for (int t = 0; t < 4; t++) {
            const __half* gp = (t < 2) ? khg : vhg;
            int cid = ((t & 1) << 8) + tid;     // 0..511
            int row = cid >> 3, c = cid & 7;
            cp16(sb + (uint32_t)(((t >> 1) << 13) + row * 128 + ((c ^ (row & 7)) << 4)),
                 gp + goff + (size_t)row * DD + c * 8);
        }
    };

    pf(0, 0); cp_commit();

    float o[8][4];
#pragma unroll
    for (int nt = 0; nt < 8; nt++)
#pragma unroll
        for (int k = 0; k < 4; k++) o[nt][k] = 0.f;
    float m0r = -INFINITY, m1r = -INFINITY, l0r = 0.f, l1r = 0.f;

    const int grow0 = q0 + wm + (lane >> 2);
    const int grow1 = grow0 + 8;
    const int nkt = 2 * qt + 2;

    for (int kt = 0; kt < nkt; kt++) {
        const int k0 = kt << 6;
        const int st = kt & 1;
        if (kt + 1 < nkt) {
            pf(kt + 1, st ^ 1); cp_commit();
            cp_wait<1>();
        } else {
            cp_wait<0>();
        }
        __syncthreads();

        const uint32_t sKHb = sKV + st * 16384;
        const uint32_t sVHb = sKHb + 8192;

        // ---- S = (Qh+Ql) K^T ----
        float s[8][4];
#pragma unroll
        for (int nt = 0; nt < 8; nt++)
#pragma unroll
            for (int k = 0; k < 4; k++) s[nt][k] = 0.f;

#pragma unroll
        for (int ks = 0; ks < 4; ks++) {
            const int ck = ks * 2 + (lane >> 4);
            uint32_t qh[4], ql[4];
            ldsm4(qh, taddr(sQH, wm + lrow, ck));
            ldsm4(ql, taddr(sQL, wm + lrow, ck));
#pragma unroll
            for (int half = 0; half < 2; half++) {
                uint32_t r0[4], r1[4];
                ldsm4(r0, taddr(sKHb, half * 32 + lrow, ck));
                ldsm4(r1, taddr(sKHb, half * 32 + 16 + lrow, ck));
                const int n0 = half * 4;
                mma2(s[n0],     qh, r0[0], r0[2]);
                mma2(s[n0 + 1], qh, r0[1], r0[3]);
                mma2(s[n0 + 2], qh, r1[0], r1[2]);
                mma2(s[n0 + 3], qh, r1[1], r1[3]);
                mma2(s[n0],     ql, r0[0], r0[2]);
                mma2(s[n0 + 1], ql, r0[1], r0[3]);
                mma2(s[n0 + 2], ql, r1[0], r1[2]);
                mma2(s[n0 + 3], ql, r1[1], r1[3]);
            }
        }

        // ---- causal mask ----
        if (k0 + 63 > grow0) {
#pragma unroll
            for (int nt = 0; nt < 8; nt++) {
                int col = k0 + nt * 8 + ((lane & 3) << 1);
                if (col > grow0)     s[nt][0] = -1e30f;
                if (col + 1 > grow0) s[nt][1] = -1e30f;
                if (col > grow1)     s[nt][2] = -1e30f;
                if (col + 1 > grow1) s[nt][3] = -1e30f;
            }
        }

        // ---- online softmax ----
        float ml0 = -INFINITY, ml1 = -INFINITY;
#pragma unroll
        for (int nt = 0; nt < 8; nt++) {
            ml0 = fmaxf(ml0, fmaxf(s[nt][0], s[nt][1]));
            ml1 = fmaxf(ml1, fmaxf(s[nt][2], s[nt][3]));
        }
        ml0 = fmaxf(ml0, __shfl_xor_sync(0xffffffffu, ml0, 1));
        ml0 = fmaxf(ml0, __shfl_xor_sync(0xffffffffu, ml0, 2));
        ml1 = fmaxf(ml1, __shfl_xor_sync(0xffffffffu, ml1, 1));
        ml1 = fmaxf(ml1, __shfl_xor_sync(0xffffffffu, ml1, 2));
        float mn0 = fmaxf(m0r, ml0), mn1 = fmaxf(m1r, ml1);
        float c0 = __expf(m0r - mn0), c1 = __expf(m1r - mn1);
        m0r = mn0; m1r = mn1;
        float rs0 = 0.f, rs1 = 0.f;
#pragma unroll
        for (int nt = 0; nt < 8; nt++) {
            s[nt][0] = __expf(s[nt][0] - mn0);
            s[nt][1] = __expf(s[nt][1] - mn0);
            s[nt][2] = __expf(s[nt][2] - mn1);
            s[nt][3] = __expf(s[nt][3] - mn1);
            rs0 += s[nt][0] + s[nt][1];
            rs1 += s[nt][2] + s[nt][3];
        }
        rs0 += __shfl_xor_sync(0xffffffffu, rs0, 1);
        rs0 += __shfl_xor_sync(0xffffffffu, rs0, 2);
        rs1 += __shfl_xor_sync(0xffffffffu, rs1, 1);
        rs1 += __shfl_xor_sync(0xffffffffu, rs1, 2);
        l0r = l0r * c0 + rs0;
        l1r = l1r * c1 + rs1;
#pragma unroll
        for (int nt = 0; nt < 8; nt++) {
            o[nt][0] *= c0; o[nt][1] *= c0;
            o[nt][2] *= c1; o[nt][3] *= c1;
        }

        // ---- O += (Ph+Pl) V ----
#pragma unroll
        for (int j = 0; j < 4; j++) {
            uint32_t aPh[4], aPl[4];
            split2h(s[2 * j][0],     s[2 * j][1],     aPh[0], aPl[0]);
            split2h(s[2 * j][2],     s[2 * j][3],     aPh[1], aPl[1]);
            split2h(s[2 * j + 1][0], s[2 * j + 1][1], aPh[2], aPl[2]);
            split2h(s[2 * j + 1][2], s[2 * j + 1][3], aPh[3], aPl[3]);
#pragma unroll
            for (int half = 0; half < 2; half++) {
                const int ck0 = half * 4 + (lane >> 4);
                const int ck1 = ck0 + 2;
                uint32_t v0[4], v1[4];
                ldsm4t(v0, taddr(sVHb, j * 16 + lrow, ck0));
                ldsm4t(v1, taddr(sVHb, j * 16 + lrow, ck1));
                const int c0i = half * 4;
                mma2(o[c0i],     aPh, v0[0], v0[1]);
                mma2(o[c0i + 1], aPh, v0[2], v0[3]);
                mma2(o[c0i + 2], aPh, v1[0], v1[1]);
                mma2(o[c0i + 3], aPh, v1[2], v1[3]);
                mma2(o[c0i],     aPl, v0[0], v0[1]);
                mma2(o[c0i + 1], aPl, v0[2], v0[3]);
                mma2(o[c0i + 2], aPl, v1[0], v1[1]);
                mma2(o[c0i + 3], aPl, v1[2], v1[3]);
            }
        }
        __syncthreads();
    }

    // ---- epilogue: normalize, split fp16 hi/lo, store merged-head [B*S, D] ----
    float inv0 = 1.f / l0r, inv1 = 1.f / l1r;
    size_t r0 = (size_t)(b * SS + grow0) * DD;
    size_t r1 = (size_t)(b * SS + grow1) * DD;
    int colb = h * HDD + ((lane & 3) << 1);
#pragma unroll
    for (int nt = 0; nt < 8; nt++) {
        int col = colb + nt * 8;
        uint32_t hp, lp;
        split2h(o[nt][0] * inv0, o[nt][1] * inv0, hp, lp);
        *(uint32_t*)(out_hi + r0 + col) = hp;
        *(uint32_t*)(out_lo + r0 + col) = lp;
        split2h(o[nt][2] * inv1, o[nt][3] * inv1, hp, lp);
        *(uint32_t*)(out_hi + r1 + col) = hp;
        *(uint32_t*)(out_lo + r1 + col) = lp;
    }
}

// ---------------------------------------------------------------------------
extern "C" void kernel_launch(void* const* d_in, const int* in_sizes, int n_in,
                              void* d_out, int out_size)
{
    const float* x  = (const float*)d_in[0];
    const float* w1 = (const float*)d_in[1];
    const float* b1 = (const float*)d_in[2];
    const float* w2 = (const float*)d_in[3];
    const float* b2 = (const float*)d_in[4];
    float* out = (float*)d_out;

    __half *xhi, *xlo, *w1h, *w2h, *qhi, *qlo, *kh, *vh, *ahi, *alo;
    cudaGetSymbolAddress((void**)&xhi, g_xhi);
    cudaGetSymbolAddress((void**)&xlo, g_xlo);
    cudaGetSymbolAddress((void**)&w1h, g_w1h);
    cudaGetSymbolAddress((void**)&w2h, g_w2h);
    cudaGetSymbolAddress((void**)&qhi, g_qhi);
    cudaGetSymbolAddress((void**)&qlo, g_qlo);
    cudaGetSymbolAddress((void**)&kh,  g_kh);
    cudaGetSymbolAddress((void**)&vh,  g_vh);
    cudaGetSymbolAddress((void**)&ahi, g_ahi);
    cudaGetSymbolAddress((void**)&alo, g_alo);

    static int inited = 0;
    if (!inited) {
        cudaFuncSetAttribute(gemm_mma<0>,
            cudaFuncAttributeMaxDynamicSharedMemorySize, GEMM_SMEM);
        cudaFuncSetAttribute(gemm_mma<1>,
            cudaFuncAttributeMaxDynamicSharedMemorySize, GEMM_SMEM);
        cudaFuncSetAttribute(flash_attn_tc,
            cudaFuncAttributeMaxDynamicSharedMemorySize, FL_SMEM);
        inited = 1;
    }

    // 0) operand prep
    split_x<<<(MM * KK / 4 + 255) / 256, 256>>>(x, xhi, xlo, MM * KK / 4);
    transpose_h<<<dim3(3 * DD / 32, KK / 32), dim3(32, 8)>>>(w1, w1h, KK, 3 * DD);
    transpose_h<<<dim3(DD / 32, KK / 32), dim3(32, 8)>>>(w2, w2h, KK, DD);

    // 1) QKV projection with fused Q-scale/split + K/V fp16 epilogue
    gemm_mma<1><<<dim3(3 * DD / 128, MM / 128), 256, GEMM_SMEM>>>(
        xhi, xlo, w1h, b1, nullptr, 3 * DD, qhi, qlo, kh, vh);

    // 2) causal flash attention on tensor cores
    flash_attn_tc<<<dim3(SS / 128, HH, BB), 256, FL_SMEM>>>(
        qhi, qlo, kh, vh, ahi, alo);

    // 3) output projection (fp32 out + bias)
    gemm_mma<0><<<dim3(DD / 128, MM / 128), 256, GEMM_SMEM>>>(
        ahi, alo, w2h, b2, out, DD, nullptr, nullptr, nullptr, nullptr);
}

// round 8
// speedup vs baseline: 7.7670x; 1.6409x over previous
#include <cuda_runtime.h>
#include <cuda_fp16.h>
#include <math.h>
#include <stdint.h>

#define BB 2
#define SS 2048
#define DD 1024
#define HH 16
#define HDD 64
#define MM (BB*SS)          // 4096
#define KK DD               // 1024

// ---------------- device scratch (no runtime allocation allowed) ----------------
__device__ __half g_xh[(size_t)MM * KK];           // x fp16
__device__ __half g_w1h[(size_t)3 * DD * KK];      // transposed [3D, K], fp16
__device__ __half g_w2h[(size_t)DD * KK];          // transposed [D, K], fp16
__device__ __half g_qh[(size_t)MM * DD];           // Q pre-scaled fp16
__device__ __half g_kh[(size_t)MM * DD];           // K fp16
__device__ __half g_vh[(size_t)MM * DD];           // V fp16
__device__ __half g_ah[(size_t)MM * DD];           // attention out fp16

// ---------------- PTX helpers (base sm_80+ ISA only) ----------
__device__ __forceinline__ uint32_t smem_u32(const void* p) {
    uint32_t a;
    asm("{ .reg .u64 t; cvta.to.shared.u64 t, %1; cvt.u32.u64 %0, t; }" : "=r"(a) : "l"(p));
    return a;
}
__device__ __forceinline__ void cp16(uint32_t dst, const void* src) {
    asm volatile("cp.async.cg.shared.global [%0], [%1], 16;" :: "r"(dst), "l"(src));
}
__device__ __forceinline__ void cp_commit() {
    asm volatile("cp.async.commit_group;" ::: "memory");
}
template <int N>
__device__ __forceinline__ void cp_wait() {
    asm volatile("cp.async.wait_group %0;" :: "n"(N) : "memory");
}
__device__ __forceinline__ void ldsm4(uint32_t* r, uint32_t addr) {
    asm volatile("ldmatrix.sync.aligned.m8n8.x4.shared.b16 {%0,%1,%2,%3}, [%4];"
                 : "=r"(r[0]), "=r"(r[1]), "=r"(r[2]), "=r"(r[3]) : "r"(addr));
}
__device__ __forceinline__ void ldsm4t(uint32_t* r, uint32_t addr) {
    asm volatile("ldmatrix.sync.aligned.m8n8.x4.trans.shared.b16 {%0,%1,%2,%3}, [%4];"
                 : "=r"(r[0]), "=r"(r[1]), "=r"(r[2]), "=r"(r[3]) : "r"(addr));
}
__device__ __forceinline__ void mma2(float* d, const uint32_t* a, uint32_t b0, uint32_t b1) {
    asm volatile(
        "mma.sync.aligned.m16n8k16.row.col.f32.f16.f16.f32 "
        "{%0,%1,%2,%3}, {%4,%5,%6,%7}, {%8,%9}, {%0,%1,%2,%3};"
        : "+f"(d[0]), "+f"(d[1]), "+f"(d[2]), "+f"(d[3])
        : "r"(a[0]), "r"(a[1]), "r"(a[2]), "r"(a[3]), "r"(b0), "r"(b1));
}
__device__ __forceinline__ uint32_t pkh(float a, float b) {
    __half2 h = __floats2half2_rn(a, b);
    return *(uint32_t*)&h;
}

// ========================== GEMM (pure fp16, single pass) ==========================
__device__ __forceinline__ uint32_t swz(int row, int c) {
    return (uint32_t)(row * 64 + ((c ^ ((row >> 1) & 3)) << 4));
}
#define TILE_BYTES 8192                 // 128 rows x 32 fp16
#define STAGE_BYTES (2 * TILE_BYTES)    // Ah, Bh
#define GEMM_SMEM  (3 * STAGE_BYTES)    // 48 KB, 3 stages

// C = Ah[M,K] @ Bh[N,K]^T + bias
// MODE 0: fp32 C.  MODE 1: QKV epilogue (Q scaled 1/8 fp16, K fp16, V fp16).
template <int MODE>
__global__ void __launch_bounds__(256, 2) gemm_mma(
    const __half* __restrict__ Ah, const __half* __restrict__ Bh,
    const float* __restrict__ bias, float* __restrict__ C, int N,
    __half* __restrict__ qd, __half* __restrict__ kd, __half* __restrict__ vd)
{
    extern __shared__ char smem[];
    const uint32_t sbase = smem_u32(smem);
    const int tid  = threadIdx.x;
    const int wid  = tid >> 5;
    const int lane = tid & 31;
    const int wm = (wid >> 2) * 64;
    const int wn = (wid & 3) * 32;
    const int m0 = blockIdx.y << 7;
    const int n0 = blockIdx.x << 7;

    const __half* srcs[2] = { Ah + (size_t)m0 * KK, Bh + (size_t)n0 * KK };

    auto prefetch = [&](int kt, int s) {
        uint32_t stb = sbase + s * STAGE_BYTES;
#pragma unroll
        for (int t = 0; t < 2; t++) {
            const __half* g = srcs[t] + kt * 32;
#pragma unroll
            for (int i = 0; i < 2; i++) {
                int cid = i * 256 + tid;
                int row = cid >> 2, c = cid & 3;
                cp16(stb + t * TILE_BYTES + swz(row, c),
                     g + (size_t)row * KK + c * 8);
            }
        }
    };

    float acc[4][4][4];
#pragma unroll
    for (int i = 0; i < 4; i++)
#pragma unroll
        for (int j = 0; j < 4; j++)
#pragma unroll
            for (int k = 0; k < 4; k++) acc[i][j][k] = 0.f;

    prefetch(0, 0); cp_commit();
    prefetch(1, 1); cp_commit();

    const int KCH = KK / 32;   // 32
    for (int kt = 0; kt < KCH; kt++) {
        const int s = kt % 3;
        if (kt == KCH - 1) cp_wait<0>(); else cp_wait<1>();
        __syncthreads();

        const uint32_t ahb = sbase + s * STAGE_BYTES;
        const uint32_t bhb = ahb + TILE_BYTES;

#pragma unroll
        for (int kh = 0; kh < 2; kh++) {
            const int lrow = lane & 15;
            const int lkc  = kh * 2 + (lane >> 4);

            uint32_t a4[4][4];
#pragma unroll
            for (int mt = 0; mt < 4; mt++)
                ldsm4(a4[mt], ahb + swz(wm + mt * 16 + lrow, lkc));
#pragma unroll
            for (int nh = 0; nh < 2; nh++) {
                uint32_t rb[4];
                ldsm4(rb, bhb + swz(wn + nh * 16 + lrow, lkc));
                const int nb = nh * 2;
#pragma unroll
                for (int mt = 0; mt < 4; mt++) {
                    mma2(acc[mt][nb],     a4[mt], rb[0], rb[2]);
                    mma2(acc[mt][nb + 1], a4[mt], rb[1], rb[3]);
                }
            }
        }
        __syncthreads();
        if (kt + 2 < KCH) { prefetch(kt + 2, (kt + 2) % 3); cp_commit(); }
    }

    if (MODE == 0) {
#pragma unroll
        for (int mt = 0; mt < 4; mt++) {
#pragma unroll
            for (int nt = 0; nt < 4; nt++) {
                int row = m0 + wm + mt * 16 + (lane >> 2);
                int col = n0 + wn + nt * 8 + ((lane & 3) << 1);
                float b0 = __ldg(bias + col), b1 = __ldg(bias + col + 1);
                float* d = acc[mt][nt];
                *(float2*)(C + (size_t)row * N + col) =
                    make_float2(d[0] + b0, d[1] + b1);
                *(float2*)(C + (size_t)(row + 8) * N + col) =
                    make_float2(d[2] + b0, d[3] + b1);
            }
        }
    } else {
        const int region = n0 >> 10;       // 0=Q, 1=K, 2=V
        const int ncol0  = n0 & 1023;
        const float qs = (region == 0) ? 0.125f : 1.0f;
        __half* dst = (region == 0) ? qd : (region == 1) ? kd : vd;
#pragma unroll
        for (int mt = 0; mt < 4; mt++) {
#pragma unroll
            for (int nt = 0; nt < 4; nt++) {
                int row  = m0 + wm + mt * 16 + (lane >> 2);
                int gcol = n0 + wn + nt * 8 + ((lane & 3) << 1);
                int col  = ncol0 + wn + nt * 8 + ((lane & 3) << 1);
                float b0 = __ldg(bias + gcol), b1 = __ldg(bias + gcol + 1);
                float* d = acc[mt][nt];
                *(uint32_t*)(dst + (size_t)row * DD + col) =
                    pkh((d[0] + b0) * qs, (d[1] + b1) * qs);
                *(uint32_t*)(dst + (size_t)(row + 8) * DD + col) =
                    pkh((d[2] + b0) * qs, (d[3] + b1) * qs);
            }
        }
    }
}

// ========================== prep kernels ==========================
__global__ void cvt_x(const float* __restrict__ in, __half* __restrict__ oh, int n4)
{
    int i = blockIdx.x * blockDim.x + threadIdx.x;
    if (i >= n4) return;
    float4 v = ((const float4*)in)[i];
    ((uint2*)oh)[i] = make_uint2(pkh(v.x, v.y), pkh(v.z, v.w));
}

// W[K,N] fp32 -> transposed fp16 [N,K]
__global__ void transpose_h(const float* __restrict__ in,
                            __half* __restrict__ hi, int K, int N)
{
    __shared__ float t[32][33];
    int bx = blockIdx.x << 5;
    int by = blockIdx.y << 5;
    int tx = threadIdx.x, ty = threadIdx.y;
#pragma unroll
    for (int i = 0; i < 32; i += 8)
        t[ty + i][tx] = in[(size_t)(by + ty + i) * N + bx + tx];
    __syncthreads();
#pragma unroll
    for (int i = 0; i < 32; i += 8) {
        int n = bx + ty + i, k = by + tx;
        hi[(size_t)n * K + k] = __float2half_rn(t[tx][ty + i]);
    }
}

// ========================== tensor-core flash attention (pure fp16) ==========================
__device__ __forceinline__ uint32_t taddr(uint32_t base, int row, int chunk) {
    return base + (uint32_t)(row * 128) + (uint32_t)((chunk ^ (row & 7)) << 4);
}

#define FL_SMEM 49152
// layout: Q 0 (16K), then 2 stages of 16K: {K 8K, V 8K}

__global__ void __launch_bounds__(256, 2) flash_attn_tc(
    const __half* __restrict__ qhg, const __half* __restrict__ khg,
    const __half* __restrict__ vhg, __half* __restrict__ outh)
{
    extern __shared__ char sm[];
    const uint32_t sQ  = smem_u32(sm);
    const uint32_t sKV = sQ + 16384;

    const int tid  = threadIdx.x;
    const int wid  = tid >> 5;
    const int lane = tid & 31;
    const int lrow = lane & 15;
    const int wm   = wid << 4;
    const int qt   = (gridDim.x - 1) - blockIdx.x;   // heavy tiles first
    const int h    = blockIdx.y;
    const int b    = blockIdx.z;
    const int q0   = qt << 7;

    // ---- Q prefetch (cp.async, pre-scaled fp16) ----
    {
        const __half* qsrc = qhg + (size_t)(b * SS + q0) * DD + h * HDD;
#pragma unroll
        for (int i = 0; i < 4; i++) {
            int cid = i * 256 + tid;          // 0..1023
            int row = cid >> 3, c = cid & 7;
            cp16(sQ + (uint32_t)(row * 128 + ((c ^ (row & 7)) << 4)),
                 qsrc + (size_t)row * DD + c * 8);
        }
        cp_commit();
    }

    // ---- K/V prefetch ----
    auto pf = [&](int kt, int st) {
        uint32_t sb = sKV + st * 16384;
        const size_t goff = (size_t)(b * SS + (kt << 6)) * DD + h * HDD;
#pragma unroll
        for (int t = 0; t < 4; t++) {
            const __half* gp = (t < 2) ? khg : vhg;
            int cid = ((t & 1) << 8) + tid;     // 0..511
            int row = cid >> 3, c = cid & 7;
            cp16(sb + (uint32_t)(((t >> 1) << 13) + row * 128 + ((c ^ (row & 7)) << 4)),
                 gp + goff + (size_t)row * DD + c * 8);
        }
    };

    pf(0, 0); cp_commit();

    float o[8][4];
#pragma unroll
    for (int nt = 0; nt < 8; nt++)
#pragma unroll
        for (int k = 0; k < 4; k++) o[nt][k] = 0.f;
    float m0r = -INFINITY, m1r = -INFINITY, l0r = 0.f, l1r = 0.f;

    const int grow0 = q0 + wm + (lane >> 2);
    const int grow1 = grow0 + 8;
    const int nkt = 2 * qt + 2;

    for (int kt = 0; kt < nkt; kt++) {
        const int k0 = kt << 6;
        const int st = kt & 1;
        if (kt + 1 < nkt) {
            pf(kt + 1, st ^ 1); cp_commit();
            cp_wait<1>();
        } else {
            cp_wait<0>();
        }
        __syncthreads();

        const uint32_t sKb = sKV + st * 16384;
        const uint32_t sVb = sKb + 8192;

        // ---- S = Q K^T ----
        float s[8][4];
#pragma unroll
        for (int nt = 0; nt < 8; nt++)
#pragma unroll
            for (int k = 0; k < 4; k++) s[nt][k] = 0.f;

#pragma unroll
        for (int ks = 0; ks < 4; ks++) {
            const int ck = ks * 2 + (lane >> 4);
            uint32_t q4[4];
            ldsm4(q4, taddr(sQ, wm + lrow, ck));
#pragma unroll
            for (int half = 0; half < 2; half++) {
                uint32_t r0[4], r1[4];
                ldsm4(r0, taddr(sKb, half * 32 + lrow, ck));
                ldsm4(r1, taddr(sKb, half * 32 + 16 + lrow, ck));
                const int n0 = half * 4;
                mma2(s[n0],     q4, r0[0], r0[2]);
                mma2(s[n0 + 1], q4, r0[1], r0[3]);
                mma2(s[n0 + 2], q4, r1[0], r1[2]);
                mma2(s[n0 + 3], q4, r1[1], r1[3]);
            }
        }

        // ---- causal mask ----
        if (k0 + 63 > grow0) {
#pragma unroll
            for (int nt = 0; nt < 8; nt++) {
                int col = k0 + nt * 8 + ((lane & 3) << 1);
                if (col > grow0)     s[nt][0] = -1e30f;
                if (col + 1 > grow0) s[nt][1] = -1e30f;
                if (col > grow1)     s[nt][2] = -1e30f;
                if (col + 1 > grow1) s[nt][3] = -1e30f;
            }
        }

        // ---- online softmax ----
        float ml0 = -INFINITY, ml1 = -INFINITY;
#pragma unroll
        for (int nt = 0; nt < 8; nt++) {
            ml0 = fmaxf(ml0, fmaxf(s[nt][0], s[nt][1]));
            ml1 = fmaxf(ml1, fmaxf(s[nt][2], s[nt][3]));
        }
        ml0 = fmaxf(ml0, __shfl_xor_sync(0xffffffffu, ml0, 1));
        ml0 = fmaxf(ml0, __shfl_xor_sync(0xffffffffu, ml0, 2));
        ml1 = fmaxf(ml1, __shfl_xor_sync(0xffffffffu, ml1, 1));
        ml1 = fmaxf(ml1, __shfl_xor_sync(0xffffffffu, ml1, 2));
        float mn0 = fmaxf(m0r, ml0), mn1 = fmaxf(m1r, ml1);
        float c0 = __expf(m0r - mn0), c1 = __expf(m1r - mn1);
        m0r = mn0; m1r = mn1;
        float rs0 = 0.f, rs1 = 0.f;
#pragma unroll
        for (int nt = 0; nt < 8; nt++) {
            s[nt][0] = __expf(s[nt][0] - mn0);
            s[nt][1] = __expf(s[nt][1] - mn0);
            s[nt][2] = __expf(s[nt][2] - mn1);
            s[nt][3] = __expf(s[nt][3] - mn1);
            rs0 += s[nt][0] + s[nt][1];
            rs1 += s[nt][2] + s[nt][3];
        }
        rs0 += __shfl_xor_sync(0xffffffffu, rs0, 1);
        rs0 += __shfl_xor_sync(0xffffffffu, rs0, 2);
        rs1 += __shfl_xor_sync(0xffffffffu, rs1, 1);
        rs1 += __shfl_xor_sync(0xffffffffu, rs1, 2);
        l0r = l0r * c0 + rs0;
        l1r = l1r * c1 + rs1;
#pragma unroll
        for (int nt = 0; nt < 8; nt++) {
            o[nt][0] *= c0; o[nt][1] *= c0;
            o[nt][2] *= c1; o[nt][3] *= c1;
        }

        // ---- O += P V ----
#pragma unroll
        for (int j = 0; j < 4; j++) {
            uint32_t aP[4];
            aP[0] = pkh(s[2 * j][0],     s[2 * j][1]);
            aP[1] = pkh(s[2 * j][2],     s[2 * j][3]);
            aP[2] = pkh(s[2 * j + 1][0], s[2 * j + 1][1]);
            aP[3] = pkh(s[2 * j + 1][2], s[2 * j + 1][3]);
#pragma unroll
            for (int half = 0; half < 2; half++) {
                const int ck0 = half * 4 + (lane >> 4);
                const int ck1 = ck0 + 2;
                uint32_t v0[4], v1[4];
                ldsm4t(v0, taddr(sVb, j * 16 + lrow, ck0));
                ldsm4t(v1, taddr(sVb, j * 16 + lrow, ck1));
                const int c0i = half * 4;
                mma2(o[c0i],     aP, v0[0], v0[1]);
                mma2(o[c0i + 1], aP, v0[2], v0[3]);
                mma2(o[c0i + 2], aP, v1[0], v1[1]);
                mma2(o[c0i + 3], aP, v1[2], v1[3]);
            }
        }
        __syncthreads();
    }

    // ---- epilogue: normalize, store fp16 merged-head [B*S, D] ----
    float inv0 = 1.f / l0r, inv1 = 1.f / l1r;
    size_t r0 = (size_t)(b * SS + grow0) * DD;
    size_t r1 = (size_t)(b * SS + grow1) * DD;
    int colb = h * HDD + ((lane & 3) << 1);
#pragma unroll
    for (int nt = 0; nt < 8; nt++) {
        int col = colb + nt * 8;
        *(uint32_t*)(outh + r0 + col) = pkh(o[nt][0] * inv0, o[nt][1] * inv0);
        *(uint32_t*)(outh + r1 + col) = pkh(o[nt][2] * inv1, o[nt][3] * inv1);
    }
}

// ---------------------------------------------------------------------------
extern "C" void kernel_launch(void* const* d_in, const int* in_sizes, int n_in,
                              void* d_out, int out_size)
{
    const float* x  = (const float*)d_in[0];
    const float* w1 = (const float*)d_in[1];
    const float* b1 = (const float*)d_in[2];
    const float* w2 = (const float*)d_in[3];
    const float* b2 = (const float*)d_in[4];
    float* out = (float*)d_out;

    __half *xh, *w1h, *w2h, *qh, *kh, *vh, *ah;
    cudaGetSymbolAddress((void**)&xh,  g_xh);
    cudaGetSymbolAddress((void**)&w1h, g_w1h);
    cudaGetSymbolAddress((void**)&w2h, g_w2h);
    cudaGetSymbolAddress((void**)&qh,  g_qh);
    cudaGetSymbolAddress((void**)&kh,  g_kh);
    cudaGetSymbolAddress((void**)&vh,  g_vh);
    cudaGetSymbolAddress((void**)&ah,  g_ah);

    static int inited = 0;
    if (!inited) {
        cudaFuncSetAttribute(gemm_mma<0>,
            cudaFuncAttributeMaxDynamicSharedMemorySize, GEMM_SMEM);
        cudaFuncSetAttribute(gemm_mma<1>,
            cudaFuncAttributeMaxDynamicSharedMemorySize, GEMM_SMEM);
        cudaFuncSetAttribute(flash_attn_tc,
            cudaFuncAttributeMaxDynamicSharedMemorySize, FL_SMEM);
        inited = 1;
    }

    // 0) operand prep
    cvt_x<<<(MM * KK / 4 + 255) / 256, 256>>>(x, xh, MM * KK / 4);
    transpose_h<<<dim3(3 * DD / 32, KK / 32), dim3(32, 8)>>>(w1, w1h, KK, 3 * DD);
    transpose_h<<<dim3(DD / 32, KK / 32), dim3(32, 8)>>>(w2, w2h, KK, DD);

    // 1) QKV projection with fused Q-scale + fp16 epilogue
    gemm_mma<1><<<dim3(3 * DD / 128, MM / 128), 256, GEMM_SMEM>>>(
        xh, w1h, b1, nullptr, 3 * DD, qh, kh, vh);

    // 2) causal flash attention on tensor cores (pure fp16)
    flash_attn_tc<<<dim3(SS / 128, HH, BB), 256, FL_SMEM>>>(qh, kh, vh, ah);

    // 3) output projection (fp32 out + bias)
    gemm_mma<0><<<dim3(DD / 128, MM / 128), 256, GEMM_SMEM>>>(
        ah, w2h, b2, out, DD, nullptr, nullptr, nullptr);
}

// round 9
// speedup vs baseline: 8.4044x; 1.0821x over previous
#include <cuda_runtime.h>
#include <cuda_fp16.h>
#include <math.h>
#include <stdint.h>

#define BB 2
#define SS 2048
#define DD 1024
#define HH 16
#define HDD 64
#define MM (BB*SS)          // 4096
#define KK DD               // 1024

// ---------------- device scratch (no runtime allocation allowed) ----------------
__device__ __half g_xh[(size_t)MM * KK];           // x fp16
__device__ __half g_w1h[(size_t)3 * DD * KK];      // transposed [3D, K], fp16
__device__ __half g_w2h[(size_t)DD * KK];          // transposed [D, K], fp16
__device__ __half g_qh[(size_t)MM * DD];           // Q pre-scaled fp16
__device__ __half g_kh[(size_t)MM * DD];           // K fp16
__device__ __half g_vh[(size_t)MM * DD];           // V fp16
__device__ __half g_ah[(size_t)MM * DD];           // attention out fp16

// ---------------- PTX helpers (base sm_80+ ISA only) ----------
__device__ __forceinline__ uint32_t smem_u32(const void* p) {
    uint32_t a;
    asm("{ .reg .u64 t; cvta.to.shared.u64 t, %1; cvt.u32.u64 %0, t; }" : "=r"(a) : "l"(p));
    return a;
}
__device__ __forceinline__ void cp16(uint32_t dst, const void* src) {
    asm volatile("cp.async.cg.shared.global [%0], [%1], 16;" :: "r"(dst), "l"(src));
}
__device__ __forceinline__ void cp_commit() {
    asm volatile("cp.async.commit_group;" ::: "memory");
}
template <int N>
__device__ __forceinline__ void cp_wait() {
    asm volatile("cp.async.wait_group %0;" :: "n"(N) : "memory");
}
__device__ __forceinline__ void ldsm4(uint32_t* r, uint32_t addr) {
    asm volatile("ldmatrix.sync.aligned.m8n8.x4.shared.b16 {%0,%1,%2,%3}, [%4];"
                 : "=r"(r[0]), "=r"(r[1]), "=r"(r[2]), "=r"(r[3]) : "r"(addr));
}
__device__ __forceinline__ void ldsm4t(uint32_t* r, uint32_t addr) {
    asm volatile("ldmatrix.sync.aligned.m8n8.x4.trans.shared.b16 {%0,%1,%2,%3}, [%4];"
                 : "=r"(r[0]), "=r"(r[1]), "=r"(r[2]), "=r"(r[3]) : "r"(addr));
}
__device__ __forceinline__ void mma2(float* d, const uint32_t* a, uint32_t b0, uint32_t b1) {
    asm volatile(
        "mma.sync.aligned.m16n8k16.row.col.f32.f16.f16.f32 "
        "{%0,%1,%2,%3}, {%4,%5,%6,%7}, {%8,%9}, {%0,%1,%2,%3};"
        : "+f"(d[0]), "+f"(d[1]), "+f"(d[2]), "+f"(d[3])
        : "r"(a[0]), "r"(a[1]), "r"(a[2]), "r"(a[3]), "r"(b0), "r"(b1));
}
__device__ __forceinline__ uint32_t pkh(float a, float b) {
    __half2 h = __floats2half2_rn(a, b);
    return *(uint32_t*)&h;
}

// 128B-row tile swizzle: chunk c (16B) of row r -> c ^ (r & 7)
__device__ __forceinline__ uint32_t taddr(uint32_t base, int row, int chunk) {
    return base + (uint32_t)(row * 128) + (uint32_t)((chunk ^ (row & 7)) << 4);
}

// ========================== GEMM (pure fp16, BK=64) ==========================
#define TILE_BYTES 16384                // 128 rows x 64 fp16 (128B rows)
#define STAGE_BYTES (2 * TILE_BYTES)    // A, B
#define GEMM_SMEM  (2 * STAGE_BYTES)    // 64 KB, 2 stages

// C = Ah[M,K] @ Bh[N,K]^T + bias
// MODE 0: fp32 C.  MODE 1: QKV epilogue (Q scaled 1/8 fp16, K fp16, V fp16).
template <int MODE>
__global__ void __launch_bounds__(256, 2) gemm_mma(
    const __half* __restrict__ Ah, const __half* __restrict__ Bh,
    const float* __restrict__ bias, float* __restrict__ C, int N,
    __half* __restrict__ qd, __half* __restrict__ kd, __half* __restrict__ vd)
{
    extern __shared__ char smem[];
    const uint32_t sbase = smem_u32(smem);
    const int tid  = threadIdx.x;
    const int wid  = tid >> 5;
    const int lane = tid & 31;
    const int wm = (wid >> 2) * 64;
    const int wn = (wid & 3) * 32;
    const int m0 = blockIdx.y << 7;
    const int n0 = blockIdx.x << 7;

    const __half* srcs[2] = { Ah + (size_t)m0 * KK, Bh + (size_t)n0 * KK };

    auto prefetch = [&](int kt, int s) {
        uint32_t stb = sbase + s * STAGE_BYTES;
#pragma unroll
        for (int t = 0; t < 2; t++) {
            const __half* g = srcs[t] + kt * 64;
#pragma unroll
            for (int i = 0; i < 4; i++) {
                int cid = i * 256 + tid;          // 0..1023
                int row = cid >> 3, c = cid & 7;
                cp16(stb + t * TILE_BYTES + (uint32_t)(row * 128 + ((c ^ (row & 7)) << 4)),
                     g + (size_t)row * KK + c * 8);
            }
        }
    };

    float acc[4][4][4];
#pragma unroll
    for (int i = 0; i < 4; i++)
#pragma unroll
        for (int j = 0; j < 4; j++)
#pragma unroll
            for (int k = 0; k < 4; k++) acc[i][j][k] = 0.f;

    prefetch(0, 0); cp_commit();
    prefetch(1, 1); cp_commit();

    const int KCH = KK / 64;   // 16
    for (int kt = 0; kt < KCH; kt++) {
        const int s = kt & 1;
        if (kt == KCH - 1) cp_wait<0>(); else cp_wait<1>();
        __syncthreads();

        const uint32_t ahb = sbase + s * STAGE_BYTES;
        const uint32_t bhb = ahb + TILE_BYTES;

#pragma unroll
        for (int kh = 0; kh < 4; kh++) {
            const int lrow = lane & 15;
            const int lkc  = kh * 2 + (lane >> 4);

            uint32_t a4[4][4];
#pragma unroll
            for (int mt = 0; mt < 4; mt++)
                ldsm4(a4[mt], taddr(ahb, wm + mt * 16 + lrow, lkc));
#pragma unroll
            for (int nh = 0; nh < 2; nh++) {
                uint32_t rb[4];
                ldsm4(rb, taddr(bhb, wn + nh * 16 + lrow, lkc));
                const int nb = nh * 2;
#pragma unroll
                for (int mt = 0; mt < 4; mt++) {
                    mma2(acc[mt][nb],     a4[mt], rb[0], rb[2]);
                    mma2(acc[mt][nb + 1], a4[mt], rb[1], rb[3]);
                }
            }
        }
        __syncthreads();
        if (kt + 2 < KCH) { prefetch(kt + 2, s); cp_commit(); }
    }

    if (MODE == 0) {
#pragma unroll
        for (int mt = 0; mt < 4; mt++) {
#pragma unroll
            for (int nt = 0; nt < 4; nt++) {
                int row = m0 + wm + mt * 16 + (lane >> 2);
                int col = n0 + wn + nt * 8 + ((lane & 3) << 1);
                float b0 = __ldg(bias + col), b1 = __ldg(bias + col + 1);
                float* d = acc[mt][nt];
                *(float2*)(C + (size_t)row * N + col) =
                    make_float2(d[0] + b0, d[1] + b1);
                *(float2*)(C + (size_t)(row + 8) * N + col) =
                    make_float2(d[2] + b0, d[3] + b1);
            }
        }
    } else {
        const int region = n0 >> 10;       // 0=Q, 1=K, 2=V
        const int ncol0  = n0 & 1023;
        const float qs = (region == 0) ? 0.125f : 1.0f;
        __half* dst = (region == 0) ? qd : (region == 1) ? kd : vd;
#pragma unroll
        for (int mt = 0; mt < 4; mt++) {
#pragma unroll
            for (int nt = 0; nt < 4; nt++) {
                int row  = m0 + wm + mt * 16 + (lane >> 2);
                int gcol = n0 + wn + nt * 8 + ((lane & 3) << 1);
                int col  = ncol0 + wn + nt * 8 + ((lane & 3) << 1);
                float b0 = __ldg(bias + gcol), b1 = __ldg(bias + gcol + 1);
                float* d = acc[mt][nt];
                *(uint32_t*)(dst + (size_t)row * DD + col) =
                    pkh((d[0] + b0) * qs, (d[1] + b1) * qs);
                *(uint32_t*)(dst + (size_t)(row + 8) * DD + col) =
                    pkh((d[2] + b0) * qs, (d[3] + b1) * qs);
            }
        }
    }
}

// ========================== fused prep kernel ==========================
// blocks [0, 4096):       x fp32 -> fp16 (float4 per thread)
// blocks [4096, 7168):    W1 [K,3072] -> transposed fp16 [3072, K]
// blocks [7168, 8192):    W2 [K,1024] -> transposed fp16 [1024, K]
__global__ void __launch_bounds__(256) prep_all(
    const float* __restrict__ x, const float* __restrict__ w1,
    const float* __restrict__ w2,
    __half* __restrict__ xh, __half* __restrict__ w1h, __half* __restrict__ w2h)
{
    __shared__ float t[32][33];
    const int bid = blockIdx.x;
    const int tid = threadIdx.x;

    if (bid < 4096) {
        int i = bid * 256 + tid;
        float4 v = ((const float4*)x)[i];
        ((uint2*)xh)[i] = make_uint2(pkh(v.x, v.y), pkh(v.z, v.w));
        return;
    }
    const float* in;
    __half* outp;
    int N, r = bid - 4096;
    if (r < 3072) { in = w1; outp = w1h; N = 3072; }
    else          { in = w2; outp = w2h; N = 1024; r -= 3072; }
    const int nb = N >> 5;
    const int bx = (r % nb) << 5;   // N offset
    const int by = (r / nb) << 5;   // K offset
    const int tx = tid & 31, ty = tid >> 5;   // ty 0..7
#pragma unroll
    for (int i = 0; i < 32; i += 8)
        t[ty + i][tx] = in[(size_t)(by + ty + i) * N + bx + tx];
    __syncthreads();
#pragma unroll
    for (int i = 0; i < 32; i += 8)
        outp[(size_t)(bx + ty + i) * KK + by + tx] = __float2half_rn(t[tx][ty + i]);
}

// ========================== tensor-core flash attention (pure fp16) ==========================
#define FL_SMEM 49152
// layout: Q 0 (16K), then 2 stages of 16K: {K 8K, V 8K}

__global__ void __launch_bounds__(256, 2) flash_attn_tc(
    const __half* __restrict__ qhg, const __half* __restrict__ khg,
    const __half* __restrict__ vhg, __half* __restrict__ outh)
{
    extern __shared__ char sm[];
    const uint32_t sQ  = smem_u32(sm);
    const uint32_t sKV = sQ + 16384;

    const int tid  = threadIdx.x;
    const int wid  = tid >> 5;
    const int lane = tid & 31;
    const int lrow = lane & 15;
    const int wm   = wid << 4;
    const int qt   = (gridDim.x - 1) - blockIdx.x;   // heavy tiles first
    const int h    = blockIdx.y;
    const int b    = blockIdx.z;
    const int q0   = qt << 7;

    // ---- Q + first K/V prefetch (one commit group) ----
    {
        const __half* qsrc = qhg + (size_t)(b * SS + q0) * DD + h * HDD;
#pragma unroll
        for (int i = 0; i < 4; i++) {
            int cid = i * 256 + tid;
            int row = cid >> 3, c = cid & 7;
            cp16(sQ + (uint32_t)(row * 128 + ((c ^ (row & 7)) << 4)),
                 qsrc + (size_t)row * DD + c * 8);
        }
    }

    auto pf = [&](int kt, int st) {
        uint32_t sb = sKV + st * 16384;
        const size_t goff = (size_t)(b * SS + (kt << 6)) * DD + h * HDD;
#pragma unroll
        for (int t = 0; t < 4; t++) {
            const __half* gp = (t < 2) ? khg : vhg;
            int cid = ((t & 1) << 8) + tid;
            int row = cid >> 3, c = cid & 7;
            cp16(sb + (uint32_t)(((t >> 1) << 13) + row * 128 + ((c ^ (row & 7)) << 4)),
                 gp + goff + (size_t)row * DD + c * 8);
        }
    };

    pf(0, 0); cp_commit();

    float o[8][4];
#pragma unroll
    for (int nt = 0; nt < 8; nt++)
#pragma unroll
        for (int k = 0; k < 4; k++) o[nt][k] = 0.f;
    float m0r = -INFINITY, m1r = -INFINITY, l0r = 0.f, l1r = 0.f;

    const int grow0 = q0 + wm + (lane >> 2);
    const int grow1 = grow0 + 8;
    const int nkt = 2 * qt + 2;

    for (int kt = 0; kt < nkt; kt++) {
        const int k0 = kt << 6;
        const int st = kt & 1;
        if (kt + 1 < nkt) {
            pf(kt + 1, st ^ 1); cp_commit();
            cp_wait<1>();
        } else {
            cp_wait<0>();
        }
        __syncthreads();

        const uint32_t sKb = sKV + st * 16384;
        const uint32_t sVb = sKb + 8192;

        // ---- S = Q K^T ----
        float s[8][4];
#pragma unroll
        for (int nt = 0; nt < 8; nt++)
#pragma unroll
            for (int k = 0; k < 4; k++) s[nt][k] = 0.f;

#pragma unroll
        for (int ks = 0; ks < 4; ks++) {
            const int ck = ks * 2 + (lane >> 4);
            uint32_t q4[4];
            ldsm4(q4, taddr(sQ, wm + lrow, ck));
#pragma unroll
            for (int half = 0; half < 2; half++) {
                uint32_t r0[4], r1[4];
                ldsm4(r0, taddr(sKb, half * 32 + lrow, ck));
                ldsm4(r1, taddr(sKb, half * 32 + 16 + lrow, ck));
                const int n0 = half * 4;
                mma2(s[n0],     q4, r0[0], r0[2]);
                mma2(s[n0 + 1], q4, r0[1], r0[3]);
                mma2(s[n0 + 2], q4, r1[0], r1[2]);
                mma2(s[n0 + 3], q4, r1[1], r1[3]);
            }
        }

        // ---- causal mask ----
        if (k0 + 63 > grow0) {
#pragma unroll
            for (int nt = 0; nt < 8; nt++) {
                int col = k0 + nt * 8 + ((lane & 3) << 1);
                if (col > grow0)     s[nt][0] = -1e30f;
                if (col + 1 > grow0) s[nt][1] = -1e30f;
                if (col > grow1)     s[nt][2] = -1e30f;
                if (col + 1 > grow1) s[nt][3] = -1e30f;
            }
        }

        // ---- online softmax ----
        float ml0 = -INFINITY, ml1 = -INFINITY;
#pragma unroll
        for (int nt = 0; nt < 8; nt++) {
            ml0 = fmaxf(ml0, fmaxf(s[nt][0], s[nt][1]));
            ml1 = fmaxf(ml1, fmaxf(s[nt][2], s[nt][3]));
        }
        ml0 = fmaxf(ml0, __shfl_xor_sync(0xffffffffu, ml0, 1));
        ml0 = fmaxf(ml0, __shfl_xor_sync(0xffffffffu, ml0, 2));
        ml1 = fmaxf(ml1, __shfl_xor_sync(0xffffffffu, ml1, 1));
        ml1 = fmaxf(ml1, __shfl_xor_sync(0xffffffffu, ml1, 2));
        float mn0 = fmaxf(m0r, ml0), mn1 = fmaxf(m1r, ml1);
        float c0 = __expf(m0r - mn0), c1 = __expf(m1r - mn1);
        m0r = mn0; m1r = mn1;
        float rs0 = 0.f, rs1 = 0.f;
#pragma unroll
        for (int nt = 0; nt < 8; nt++) {
            s[nt][0] = __expf(s[nt][0] - mn0);
            s[nt][1] = __expf(s[nt][1] - mn0);
            s[nt][2] = __expf(s[nt][2] - mn1);
            s[nt][3] = __expf(s[nt][3] - mn1);
            rs0 += s[nt][0] + s[nt][1];
            rs1 += s[nt][2] + s[nt][3];
        }
        rs0 += __shfl_xor_sync(0xffffffffu, rs0, 1);
        rs0 += __shfl_xor_sync(0xffffffffu, rs0, 2);
        rs1 += __shfl_xor_sync(0xffffffffu, rs1, 1);
        rs1 += __shfl_xor_sync(0xffffffffu, rs1, 2);
        l0r = l0r * c0 + rs0;
        l1r = l1r * c1 + rs1;
        // skip exact-noop rescale (c == 1.0 when max unchanged; __expf(0)=1 exactly)
        if (!__all_sync(0xffffffffu, (c0 == 1.f) && (c1 == 1.f))) {
#pragma unroll
            for (int nt = 0; nt < 8; nt++) {
                o[nt][0] *= c0; o[nt][1] *= c0;
                o[nt][2] *= c1; o[nt][3] *= c1;
            }
        }

        // ---- O += P V ----
#pragma unroll
        for (int j = 0; j < 4; j++) {
            uint32_t aP[4];
            aP[0] = pkh(s[2 * j][0],     s[2 * j][1]);
            aP[1] = pkh(s[2 * j][2],     s[2 * j][3]);
            aP[2] = pkh(s[2 * j + 1][0], s[2 * j + 1][1]);
            aP[3] = pkh(s[2 * j + 1][2], s[2 * j + 1][3]);
#pragma unroll
            for (int half = 0; half < 2; half++) {
                const int ck0 = half * 4 + (lane >> 4);
                const int ck1 = ck0 + 2;
                uint32_t v0[4], v1[4];
                ldsm4t(v0, taddr(sVb, j * 16 + lrow, ck0));
                ldsm4t(v1, taddr(sVb, j * 16 + lrow, ck1));
                const int c0i = half * 4;
                mma2(o[c0i],     aP, v0[0], v0[1]);
                mma2(o[c0i + 1], aP, v0[2], v0[3]);
                mma2(o[c0i + 2], aP, v1[0], v1[1]);
                mma2(o[c0i + 3], aP, v1[2], v1[3]);
            }
        }
        __syncthreads();
    }

    // ---- epilogue: normalize, store fp16 merged-head [B*S, D] ----
    float inv0 = 1.f / l0r, inv1 = 1.f / l1r;
    size_t r0 = (size_t)(b * SS + grow0) * DD;
    size_t r1 = (size_t)(b * SS + grow1) * DD;
    int colb = h * HDD + ((lane & 3) << 1);
#pragma unroll
    for (int nt = 0; nt < 8; nt++) {
        int col = colb + nt * 8;
        *(uint32_t*)(outh + r0 + col) = pkh(o[nt][0] * inv0, o[nt][1] * inv0);
        *(uint32_t*)(outh + r1 + col) = pkh(o[nt][2] * inv1, o[nt][3] * inv1);
    }
}

// ---------------------------------------------------------------------------
extern "C" void kernel_launch(void* const* d_in, const int* in_sizes, int n_in,
                              void* d_out, int out_size)
{
    const float* x  = (const float*)d_in[0];
    const float* w1 = (const float*)d_in[1];
    const float* b1 = (const float*)d_in[2];
    const float* w2 = (const float*)d_in[3];
    const float* b2 = (const float*)d_in[4];
    float* out = (float*)d_out;

    __half *xh, *w1h, *w2h, *qh, *kh, *vh, *ah;
    cudaGetSymbolAddress((void**)&xh,  g_xh);
    cudaGetSymbolAddress((void**)&w1h, g_w1h);
    cudaGetSymbolAddress((void**)&w2h, g_w2h);
    cudaGetSymbolAddress((void**)&qh,  g_qh);
    cudaGetSymbolAddress((void**)&kh,  g_kh);
    cudaGetSymbolAddress((void**)&vh,  g_vh);
    cudaGetSymbolAddress((void**)&ah,  g_ah);

    static int inited = 0;
    if (!inited) {
        cudaFuncSetAttribute(gemm_mma<0>,
            cudaFuncAttributeMaxDynamicSharedMemorySize, GEMM_SMEM);
        cudaFuncSetAttribute(gemm_mma<1>,
            cudaFuncAttributeMaxDynamicSharedMemorySize, GEMM_SMEM);
        cudaFuncSetAttribute(flash_attn_tc,
            cudaFuncAttributeMaxDynamicSharedMemorySize, FL_SMEM);
        inited = 1;
    }

    // 0) fused operand prep (x convert + W1/W2 transpose-convert)
    prep_all<<<8192, 256>>>(x, w1, w2, xh, w1h, w2h);

    // 1) QKV projection with fused Q-scale + fp16 epilogue
    gemm_mma<1><<<dim3(3 * DD / 128, MM / 128), 256, GEMM_SMEM>>>(
        xh, w1h, b1, nullptr, 3 * DD, qh, kh, vh);

    // 2) causal flash attention on tensor cores (pure fp16)
    flash_attn_tc<<<dim3(SS / 128, HH, BB), 256, FL_SMEM>>>(qh, kh, vh, ah);

    // 3) output projection (fp32 out + bias)
    gemm_mma<0><<<dim3(DD / 128, MM / 128), 256, GEMM_SMEM>>>(
        ah, w2h, b2, out, DD, nullptr, nullptr, nullptr);
}